// round 7
// baseline (speedup 1.0000x reference)
#include <cuda_runtime.h>
#include <cstdint>

#define N_NODES 100000
#define N_EDGES 3200000
#define IN_FEATS 512
#define HIDDEN 16
#define OUT_FEATS 128
#define N_CLASSES 3

// ---------------- scratch (device globals; no allocation) ----------------
__device__ __align__(16) float g_h1 [N_NODES * HIDDEN];            // ns*(feat@W1)
__device__ __align__(16) float g_agg1[N_NODES * HIDDEN];
__device__ __align__(16) float g_x1 [N_NODES * HIDDEN];            // relu(nd*agg1+b1)
__device__ __align__(16) float g_h2 [(size_t)N_NODES * OUT_FEATS]; // ns*(x1@W2)
__device__ __align__(16) float g_agg2[(size_t)N_NODES * OUT_FEATS];
__device__ __align__(16) float g_ns [N_NODES];
__device__ __align__(16) float g_nd [N_NODES];
__device__ __align__(16) int   g_degs[N_NODES];
__device__ __align__(16) int   g_degd[N_NODES];

// red.v4: proven semantically identical to 16x scalar atomicAdd (R4 == R5 bitwise rel_err)
__device__ __forceinline__ void red_add_v4(float* p, float4 v) {
    asm volatile("red.global.add.v4.f32 [%0], {%1,%2,%3,%4};"
                 :: "l"(p), "f"(v.x), "f"(v.y), "f"(v.z), "f"(v.w) : "memory");
}

// ---------------- zero scratch ----------------
__global__ void zero_kernel() {
    int i = blockIdx.x * blockDim.x + threadIdx.x;      // grid covers 3.2M
    if (i < (N_NODES * OUT_FEATS) / 4)
        ((float4*)g_agg2)[i] = make_float4(0.f, 0.f, 0.f, 0.f);
    if (i < (N_NODES * HIDDEN) / 4)
        ((float4*)g_agg1)[i] = make_float4(0.f, 0.f, 0.f, 0.f);
    if (i < N_NODES / 4) {
        ((int4*)g_degs)[i] = make_int4(0, 0, 0, 0);
        ((int4*)g_degd)[i] = make_int4(0, 0, 0, 0);
    }
}

// ---------------- degrees ----------------
__global__ void deg_kernel(const int* __restrict__ src, const int* __restrict__ dst) {
    int e = blockIdx.x * blockDim.x + threadIdx.x;
    if (e < N_EDGES) {
        atomicAdd(&g_degs[src[e]], 1);
        atomicAdd(&g_degd[dst[e]], 1);
    }
}

__global__ void norm_kernel() {
    int n = blockIdx.x * blockDim.x + threadIdx.x;
    if (n < N_NODES) {
        g_ns[n] = rsqrtf(fmaxf((float)g_degs[n], 1.0f));
        g_nd[n] = rsqrtf(fmaxf((float)g_degd[n], 1.0f));
    }
}

// ---------------- layer 1 projection: h1[n][j] = ns[n] * sum_k feat[n][k]*W1[k][j] ----
__global__ __launch_bounds__(256)
void proj1_kernel(const float* __restrict__ feat, const float* __restrict__ W1) {
    __shared__ float w[IN_FEATS * HIDDEN];       // 32KB, layout as-is [k*16+j]
    for (int i = threadIdx.x; i < IN_FEATS * HIDDEN; i += 256) w[i] = W1[i];
    __syncthreads();
    int i = blockIdx.x * 256 + threadIdx.x;      // 1.6M threads exactly
    int n = i >> 4, j = i & 15;
    float s = g_ns[n];
    float acc = 0.f;
    #pragma unroll 8
    for (int k = 0; k < IN_FEATS; k++)
        acc = fmaf(feat[(size_t)n * IN_FEATS + k], w[k * HIDDEN + j], acc);
    g_h1[i] = s * acc;
}

// ---------------- layer 1 aggregation: agg1[dst] += h1[src] (16 floats) ----------
__global__ void scat1_kernel(const int* __restrict__ src, const int* __restrict__ dst) {
    int e = blockIdx.x * blockDim.x + threadIdx.x;
    if (e >= N_EDGES) return;
    int s = src[e], d = dst[e];
    const float4* p4 = (const float4*)(g_h1 + (size_t)s * HIDDEN);
    float* base = g_agg1 + (size_t)d * HIDDEN;
    red_add_v4(base + 0,  p4[0]);
    red_add_v4(base + 4,  p4[1]);
    red_add_v4(base + 8,  p4[2]);
    red_add_v4(base + 12, p4[3]);
}

// ---------------- x1 = relu(nd*agg1 + b1) ----------------
__global__ void relu1_kernel(const float* __restrict__ b1) {
    int i = blockIdx.x * blockDim.x + threadIdx.x;
    if (i < N_NODES * HIDDEN) {
        int n = i >> 4, j = i & 15;
        g_x1[i] = fmaxf(fmaf(g_nd[n], g_agg1[i], b1[j]), 0.f);
    }
}

// ---------------- layer 2 projection: h2[n][o] = ns[n] * sum_k x1[n][k]*W2[k][o] ----
__global__ __launch_bounds__(256)
void proj2_kernel(const float* __restrict__ W2) {
    __shared__ float w[HIDDEN * OUT_FEATS];      // 8KB, [k*128+o]
    for (int i = threadIdx.x; i < HIDDEN * OUT_FEATS; i += 256) w[i] = W2[i];
    __syncthreads();
    int i = blockIdx.x * 256 + threadIdx.x;      // 12.8M threads exactly
    int n = i >> 7, o = i & 127;
    float s = g_ns[n];
    float acc = 0.f;
    #pragma unroll
    for (int k = 0; k < HIDDEN; k++)
        acc = fmaf(g_x1[n * HIDDEN + k], w[k * OUT_FEATS + o], acc);
    g_h2[i] = s * acc;
}

// ---------------- layer 2 aggregation: agg2[dst] += h2[src] (128 floats) ----------
// thread per (edge, 4-float chunk): 32 threads cover one edge's 128 floats.
__global__ void scat2_kernel(const int* __restrict__ src, const int* __restrict__ dst) {
    long long i = (long long)blockIdx.x * blockDim.x + threadIdx.x;
    if (i >= (long long)N_EDGES * 32) return;
    int e = (int)(i >> 5), t = (int)(i & 31);
    int s = src[e], d = dst[e];
    float4 v = *(const float4*)(g_h2 + (size_t)s * OUT_FEATS + 4 * t);
    red_add_v4(g_agg2 + (size_t)d * OUT_FEATS + 4 * t, v);
}

// ---------------- out[n][c] = sum_o (nd[n]*agg2[n][o] + b2[o]) * Wfc[o][c] + bfc[c] --
__global__ void fc_kernel(const float* __restrict__ b2, const float* __restrict__ Wfc,
                          const float* __restrict__ bfc, float* __restrict__ out) {
    __shared__ float wf[OUT_FEATS * N_CLASSES];
    __shared__ float bb[OUT_FEATS];
    for (int i = threadIdx.x; i < OUT_FEATS * N_CLASSES; i += blockDim.x) wf[i] = Wfc[i];
    for (int i = threadIdx.x; i < OUT_FEATS; i += blockDim.x) bb[i] = b2[i];
    __syncthreads();
    int n = blockIdx.x * blockDim.x + threadIdx.x;
    if (n >= N_NODES) return;
    float dn = g_nd[n];
    float c0 = bfc[0], c1 = bfc[1], c2 = bfc[2];
    #pragma unroll 4
    for (int o = 0; o < OUT_FEATS; o++) {
        float x = fmaf(dn, g_agg2[(size_t)n * OUT_FEATS + o], bb[o]);
        c0 = fmaf(x, wf[o * 3 + 0], c0);
        c1 = fmaf(x, wf[o * 3 + 1], c1);
        c2 = fmaf(x, wf[o * 3 + 2], c2);
    }
    out[n * 3 + 0] = c0;
    out[n * 3 + 1] = c1;
    out[n * 3 + 2] = c2;
}

// ---------------- launch (positional inputs; proven == size-matching) ----------------
extern "C" void kernel_launch(void* const* d_in, const int* in_sizes, int n_in,
                              void* d_out, int out_size) {
    const float* feat = (const float*)d_in[0];
    const int*   src  = (const int*)d_in[1];   // int32 (proven R3==R4)
    const int*   dst  = (const int*)d_in[2];
    const float* W1   = (const float*)d_in[3];
    const float* b1   = (const float*)d_in[4];
    const float* W2   = (const float*)d_in[5];
    const float* b2   = (const float*)d_in[6];
    const float* Wfc  = (const float*)d_in[7];
    const float* bfc  = (const float*)d_in[8];
    float*       out  = (float*)d_out;

    const int TB = 256;
    int zb  = (N_NODES * OUT_FEATS / 4 + TB - 1) / TB;           // 12500
    int eb  = (N_EDGES + TB - 1) / TB;                           // 12500
    int nb  = (N_NODES + TB - 1) / TB;                           // 391
    int p1b = N_NODES * HIDDEN / TB;                             // 6250
    int r1b = (N_NODES * HIDDEN + TB - 1) / TB;                  // 6250
    int p2b = N_NODES * OUT_FEATS / TB;                          // 50000
    long long s2t = (long long)N_EDGES * 32;
    int s2b = (int)((s2t + TB - 1) / TB);                        // 400000

    zero_kernel <<<zb, TB>>>();
    deg_kernel  <<<eb, TB>>>(src, dst);
    norm_kernel <<<nb, TB>>>();
    proj1_kernel<<<p1b, TB>>>(feat, W1);
    scat1_kernel<<<eb, TB>>>(src, dst);
    relu1_kernel<<<r1b, TB>>>(b1);
    proj2_kernel<<<p2b, TB>>>(W2);
    scat2_kernel<<<s2b, TB>>>(src, dst);
    fc_kernel   <<<nb, TB>>>(b2, Wfc, bfc, out);
}

// round 8
// speedup vs baseline: 2.6556x; 2.6556x over previous
#include <cuda_runtime.h>
#include <cstdint>

#define N_NODES 100000
#define N_EDGES 3200000
#define IN_FEATS 512
#define HIDDEN 16
#define OUT_FEATS 128
#define N_CLASSES 3

// ---------------- scratch (device globals; touched ONLY from device code) ----------
__device__ __align__(16) float g_p1 [N_NODES * HIDDEN];   // ns * (feat @ W1)
__device__ __align__(16) float g_agg1[N_NODES * HIDDEN];  // layer-1 aggregate
__device__ __align__(16) float g_q  [N_NODES * HIDDEN];   // ns * relu(nd*agg1 + b1)
__device__ __align__(16) float g_agg2[N_NODES * HIDDEN];  // layer-2 aggregate (16-dim)
__device__ __align__(16) float g_ns [N_NODES];
__device__ __align__(16) float g_nd [N_NODES];
__device__ __align__(16) int   g_degs[N_NODES];
__device__ __align__(16) int   g_degd[N_NODES];
__device__ __align__(16) float g_Wc [HIDDEN * N_CLASSES]; // W2 @ Wfc
__device__ __align__(16) float g_bc [N_CLASSES];          // b2 @ Wfc + bfc

__device__ __forceinline__ void red_add_v4(float* p, float4 v) {
    asm volatile("red.global.add.v4.f32 [%0], {%1,%2,%3,%4};"
                 :: "l"(p), "f"(v.x), "f"(v.y), "f"(v.z), "f"(v.w) : "memory");
}

// ---------------- zero scratch ----------------
__global__ void zero_kernel() {
    int i = blockIdx.x * blockDim.x + threadIdx.x;
    const int NV4 = N_NODES * HIDDEN / 4;   // 400000
    if (i < NV4) {
        ((float4*)g_agg1)[i] = make_float4(0.f, 0.f, 0.f, 0.f);
        ((float4*)g_agg2)[i] = make_float4(0.f, 0.f, 0.f, 0.f);
    }
    if (i < N_NODES / 4) {
        ((int4*)g_degs)[i] = make_int4(0, 0, 0, 0);
        ((int4*)g_degd)[i] = make_int4(0, 0, 0, 0);
    }
}

// ---------------- degrees ----------------
__global__ void deg_kernel(const int* __restrict__ src, const int* __restrict__ dst) {
    int e = blockIdx.x * blockDim.x + threadIdx.x;
    if (e < N_EDGES) {
        atomicAdd(&g_degs[src[e]], 1);
        atomicAdd(&g_degd[dst[e]], 1);
    }
}

__global__ void norm_kernel() {
    int n = blockIdx.x * blockDim.x + threadIdx.x;
    if (n < N_NODES) {
        g_ns[n] = rsqrtf(fmaxf((float)g_degs[n], 1.0f));
        g_nd[n] = rsqrtf(fmaxf((float)g_degd[n], 1.0f));
    }
}

// ---------------- Wc = W2 @ Wfc, bc = b2 @ Wfc + bfc ----------------
__global__ void wc_kernel(const float* __restrict__ W2, const float* __restrict__ b2,
                          const float* __restrict__ Wfc, const float* __restrict__ bfc) {
    int t = threadIdx.x;
    if (t < HIDDEN * N_CLASSES) {
        int k = t / N_CLASSES, c = t % N_CLASSES;
        float s = 0.f;
        for (int o = 0; o < OUT_FEATS; o++)
            s += W2[k * OUT_FEATS + o] * Wfc[o * N_CLASSES + c];
        g_Wc[t] = s;
    }
    if (t < N_CLASSES) {
        float s = bfc[t];
        for (int o = 0; o < OUT_FEATS; o++)
            s += b2[o] * Wfc[o * N_CLASSES + t];
        g_bc[t] = s;
    }
}

// ---------------- GEMM1: p1[n][j] = ns[n] * sum_k feat[n][k] * W1[k][j] ----------------
// Warp computes 4 rows; feature row read once (coalesced float4); W1^T in SMEM;
// 62-shuffle fold reduction -> lane l holds ids {2l, 2l+1}; coalesced float2 store.
__global__ __launch_bounds__(256, 2)
void gemm1_kernel(const float* __restrict__ feat, const float* __restrict__ W1) {
    __shared__ __align__(16) float ws[HIDDEN * IN_FEATS];  // ws[j*512 + k]
    int tid = threadIdx.x;
    #pragma unroll 4
    for (int idx = tid; idx < HIDDEN * IN_FEATS; idx += 256) {
        int k = idx >> 4, j = idx & 15;       // W1 is [512][16] row-major
        ws[j * IN_FEATS + k] = W1[idx];
    }
    __syncthreads();

    int lane = tid & 31;
    int warp = tid >> 5;
    int row0 = blockIdx.x * 32 + warp * 4;    // 100000 = 3125 * 32, exact

    const float4* f4 = (const float4*)feat;
    const float4* w4 = (const float4*)ws;

    float v[64];
    #pragma unroll
    for (int i = 0; i < 64; i++) v[i] = 0.f;

    #pragma unroll
    for (int i = 0; i < 4; i++) {
        int col = i * 32 + lane;
        float4 a0 = f4[(size_t)(row0 + 0) * 128 + col];
        float4 a1 = f4[(size_t)(row0 + 1) * 128 + col];
        float4 a2 = f4[(size_t)(row0 + 2) * 128 + col];
        float4 a3 = f4[(size_t)(row0 + 3) * 128 + col];
        #pragma unroll
        for (int j = 0; j < 16; j++) {
            float4 w = w4[j * 128 + col];
            v[ 0 + j] = fmaf(a0.x, w.x, fmaf(a0.y, w.y, fmaf(a0.z, w.z, fmaf(a0.w, w.w, v[ 0 + j]))));
            v[16 + j] = fmaf(a1.x, w.x, fmaf(a1.y, w.y, fmaf(a1.z, w.z, fmaf(a1.w, w.w, v[16 + j]))));
            v[32 + j] = fmaf(a2.x, w.x, fmaf(a2.y, w.y, fmaf(a2.z, w.z, fmaf(a2.w, w.w, v[32 + j]))));
            v[48 + j] = fmaf(a3.x, w.x, fmaf(a3.y, w.y, fmaf(a3.z, w.z, fmaf(a3.w, w.w, v[48 + j]))));
        }
    }

    #pragma unroll
    for (int step = 0; step < 5; step++) {
        const int half = 32 >> step;
        const int bit  = 16 >> step;
        bool up = (lane & bit) != 0;
        #pragma unroll
        for (int i = 0; i < half; i++) {
            float send = up ? v[i] : v[i + half];
            float got  = __shfl_xor_sync(0xffffffffu, send, bit);
            v[i] = (up ? v[i + half] : v[i]) + got;
        }
    }
    int id0 = 2 * lane;
    int row = row0 + (id0 >> 4);
    float s = g_ns[row];
    float2 o; o.x = v[0] * s; o.y = v[1] * s;
    *(float2*)(g_p1 + (size_t)row0 * 16 + id0) = o;
}

// ---------------- layer-1 scatter: agg1[dst] += p1[src] ----------------
__global__ void scat1_kernel(const int* __restrict__ src, const int* __restrict__ dst) {
    int e = blockIdx.x * blockDim.x + threadIdx.x;
    if (e >= N_EDGES) return;
    int s = src[e], d = dst[e];
    const float4* p4 = (const float4*)(g_p1 + (size_t)s * HIDDEN);
    float* base = g_agg1 + (size_t)d * HIDDEN;
    red_add_v4(base + 0,  p4[0]);
    red_add_v4(base + 4,  p4[1]);
    red_add_v4(base + 8,  p4[2]);
    red_add_v4(base + 12, p4[3]);
}

// ---------------- q = ns * relu(nd * agg1 + b1) ----------------
__global__ void x1q_kernel(const float* __restrict__ b1) {
    int n = blockIdx.x * blockDim.x + threadIdx.x;
    if (n >= N_NODES) return;
    float s  = g_ns[n];
    float dn = g_nd[n];
    const float4* a4 = (const float4*)g_agg1;
    float4* q4 = (float4*)g_q;
    #pragma unroll
    for (int t = 0; t < 4; t++) {
        float4 a = a4[n * 4 + t];
        float4 o;
        o.x = s * fmaxf(fmaf(dn, a.x, b1[4*t+0]), 0.f);
        o.y = s * fmaxf(fmaf(dn, a.y, b1[4*t+1]), 0.f);
        o.z = s * fmaxf(fmaf(dn, a.z, b1[4*t+2]), 0.f);
        o.w = s * fmaxf(fmaf(dn, a.w, b1[4*t+3]), 0.f);
        q4[n * 4 + t] = o;
    }
}

// ---------------- layer-2 scatter: agg2[dst] += q[src] (16-dim!) ----------------
__global__ void scat2_kernel(const int* __restrict__ src, const int* __restrict__ dst) {
    int e = blockIdx.x * blockDim.x + threadIdx.x;
    if (e >= N_EDGES) return;
    int s = src[e], d = dst[e];
    const float4* p4 = (const float4*)(g_q + (size_t)s * HIDDEN);
    float* base = g_agg2 + (size_t)d * HIDDEN;
    red_add_v4(base + 0,  p4[0]);
    red_add_v4(base + 4,  p4[1]);
    red_add_v4(base + 8,  p4[2]);
    red_add_v4(base + 12, p4[3]);
}

// ---------------- out[n][c] = nd[n] * dot(agg2[n], Wc[:,c]) + bc[c] ----------------
__global__ void final_kernel(float* __restrict__ out) {
    int n = blockIdx.x * blockDim.x + threadIdx.x;
    if (n >= N_NODES) return;
    float dn = g_nd[n];
    const float4* a4 = (const float4*)g_agg2;
    float av[16];
    #pragma unroll
    for (int t = 0; t < 4; t++) {
        float4 a = a4[n * 4 + t];
        av[4 * t + 0] = a.x; av[4 * t + 1] = a.y;
        av[4 * t + 2] = a.z; av[4 * t + 3] = a.w;
    }
    float c0 = 0.f, c1 = 0.f, c2 = 0.f;
    #pragma unroll
    for (int k = 0; k < 16; k++) {
        float x = av[k];
        c0 = fmaf(x, g_Wc[k * 3 + 0], c0);
        c1 = fmaf(x, g_Wc[k * 3 + 1], c1);
        c2 = fmaf(x, g_Wc[k * 3 + 2], c2);
    }
    out[n * 3 + 0] = fmaf(dn, c0, g_bc[0]);
    out[n * 3 + 1] = fmaf(dn, c1, g_bc[1]);
    out[n * 3 + 2] = fmaf(dn, c2, g_bc[2]);
}

// ---------------- launch ----------------
extern "C" void kernel_launch(void* const* d_in, const int* in_sizes, int n_in,
                              void* d_out, int out_size) {
    const float* feat = (const float*)d_in[0];
    const int*   src  = (const int*)d_in[1];   // int32 (empirically proven)
    const int*   dst  = (const int*)d_in[2];
    const float* W1   = (const float*)d_in[3];
    const float* b1   = (const float*)d_in[4];
    const float* W2   = (const float*)d_in[5];
    const float* b2   = (const float*)d_in[6];
    const float* Wfc  = (const float*)d_in[7];
    const float* bfc  = (const float*)d_in[8];
    float*       out  = (float*)d_out;

    const int TB = 256;
    int zb = (N_NODES * HIDDEN / 4 + TB - 1) / TB;
    int eb = (N_EDGES + TB - 1) / TB;
    int nb = (N_NODES + TB - 1) / TB;

    zero_kernel <<<zb, TB>>>();
    deg_kernel  <<<eb, TB>>>(src, dst);
    norm_kernel <<<nb, TB>>>();
    wc_kernel   <<<1, 64>>>(W2, b2, Wfc, bfc);
    gemm1_kernel<<<N_NODES / 32, 256>>>(feat, W1);
    scat1_kernel<<<eb, TB>>>(src, dst);
    x1q_kernel  <<<nb, TB>>>(b1);
    scat2_kernel<<<eb, TB>>>(src, dst);
    final_kernel<<<nb, TB>>>(out);
}

// round 9
// speedup vs baseline: 3.7017x; 1.3939x over previous
#include <cuda_runtime.h>
#include <cstdint>

#define N_NODES 100000
#define N_EDGES 3200000
#define IN_FEATS 512
#define HIDDEN 16
#define OUT_FEATS 128
#define N_CLASSES 3

#define SCAN_BLK 512
#define N_SCAN_BLKS ((N_NODES + SCAN_BLK) / SCAN_BLK + 1)   // covers N_NODES+1 entries

// ---------------- scratch (device globals; touched ONLY from device code) ----------
__device__ __align__(16) float g_p1 [N_NODES * HIDDEN];   // ns * (feat @ W1)
__device__ __align__(16) float g_q  [N_NODES * HIDDEN];   // ns * relu(nd*agg1 + b1)
__device__ __align__(16) float g_ns [N_NODES];
__device__ __align__(16) float g_nd [N_NODES];
__device__ __align__(16) int   g_degs[N_NODES];
__device__ __align__(16) int   g_degd[N_NODES];           // in-degree, then permute cursor
__device__ __align__(16) int   g_rowptr[N_NODES + 1];
__device__ __align__(16) int   g_blksum[256];
__device__ __align__(16) int   g_csrc[N_EDGES];           // CSR (by dst): source node ids
__device__ __align__(16) float g_Wc [HIDDEN * N_CLASSES]; // W2 @ Wfc
__device__ __align__(16) float g_bc [N_CLASSES];          // b2 @ Wfc + bfc

// ---------------- zero degree arrays ----------------
__global__ void zero_kernel() {
    int i = blockIdx.x * blockDim.x + threadIdx.x;
    if (i < N_NODES / 4) {
        ((int4*)g_degs)[i] = make_int4(0, 0, 0, 0);
        ((int4*)g_degd)[i] = make_int4(0, 0, 0, 0);
    }
}

// ---------------- degree histogram, 4 edges per thread ----------------
__global__ void deg_kernel(const int* __restrict__ src, const int* __restrict__ dst) {
    int t = blockIdx.x * blockDim.x + threadIdx.x;      // 800K threads
    if (t >= N_EDGES / 4) return;
    int4 s4 = ((const int4*)src)[t];
    int4 d4 = ((const int4*)dst)[t];
    atomicAdd(&g_degs[s4.x], 1); atomicAdd(&g_degs[s4.y], 1);
    atomicAdd(&g_degs[s4.z], 1); atomicAdd(&g_degs[s4.w], 1);
    atomicAdd(&g_degd[d4.x], 1); atomicAdd(&g_degd[d4.y], 1);
    atomicAdd(&g_degd[d4.z], 1); atomicAdd(&g_degd[d4.w], 1);
}

// ---------------- norms everywhere; block 0 additionally computes Wc, bc ----------
__global__ __launch_bounds__(384)
void norm_wc_kernel(const float* __restrict__ W2, const float* __restrict__ b2,
                    const float* __restrict__ Wfc, const float* __restrict__ bfc) {
    int n = blockIdx.x * 384 + threadIdx.x;
    if (n < N_NODES) {
        g_ns[n] = rsqrtf(fmaxf((float)g_degs[n], 1.0f));
        g_nd[n] = rsqrtf(fmaxf((float)g_degd[n], 1.0f));
    }
    if (blockIdx.x == 0) {
        // Wc[k][c] = sum_o W2[k][o] * Wfc[o][c]; 48 outputs x 8 partial lanes
        __shared__ float part[384];
        int t = threadIdx.x;               // t = out*8 + chunk
        int o0 = (t & 7) * 16;             // chunk covers 16 o's
        int idx = t >> 3;                  // 0..47
        int k = idx / N_CLASSES, c = idx % N_CLASSES;
        float s = 0.f;
        #pragma unroll
        for (int o = 0; o < 16; o++)
            s += W2[k * OUT_FEATS + o0 + o] * Wfc[(o0 + o) * N_CLASSES + c];
        part[t] = s;
        __syncthreads();
        if ((t & 7) == 0) {
            float tot = 0.f;
            #pragma unroll
            for (int u = 0; u < 8; u++) tot += part[t + u];
            g_Wc[idx] = tot;
        }
        if (t < N_CLASSES) {
            float s2 = bfc[t];
            for (int o = 0; o < OUT_FEATS; o++)
                s2 += b2[o] * Wfc[o * N_CLASSES + t];
            g_bc[t] = s2;
        }
    }
}

// ---------------- scan stage 1: per-block exclusive scan of g_degd ----------------
__global__ __launch_bounds__(SCAN_BLK)
void scan1_kernel() {
    __shared__ int sh[SCAN_BLK];
    int i = blockIdx.x * SCAN_BLK + threadIdx.x;
    int v = (i < N_NODES) ? g_degd[i] : 0;
    sh[threadIdx.x] = v;
    __syncthreads();
    #pragma unroll
    for (int off = 1; off < SCAN_BLK; off <<= 1) {
        int t = (threadIdx.x >= off) ? sh[threadIdx.x - off] : 0;
        __syncthreads();
        sh[threadIdx.x] += t;
        __syncthreads();
    }
    if (i <= N_NODES) g_rowptr[i] = sh[threadIdx.x] - v;   // exclusive
    if (threadIdx.x == SCAN_BLK - 1) g_blksum[blockIdx.x] = sh[SCAN_BLK - 1];
}

// ---------------- scan stage 2: exclusive scan of block sums (in place) ----------
__global__ __launch_bounds__(256)
void scan2_kernel() {
    __shared__ int sh[256];
    int t = threadIdx.x;
    int v = (t < N_SCAN_BLKS) ? g_blksum[t] : 0;
    sh[t] = v;
    __syncthreads();
    #pragma unroll
    for (int off = 1; off < 256; off <<= 1) {
        int x = (t >= off) ? sh[t - off] : 0;
        __syncthreads();
        sh[t] += x;
        __syncthreads();
    }
    g_blksum[t] = sh[t] - v;   // exclusive block offsets
}

// ---------------- scan stage 3: add block offsets; re-zero degd as cursor --------
__global__ __launch_bounds__(SCAN_BLK)
void scan3_kernel() {
    int i = blockIdx.x * SCAN_BLK + threadIdx.x;
    if (i <= N_NODES) g_rowptr[i] += g_blksum[blockIdx.x];
    if (i < N_NODES)  g_degd[i] = 0;
}

// ---------------- CSR permute: csrc[rowptr[d] + cursor[d]++] = src ----------------
__global__ void permute_kernel(const int* __restrict__ src, const int* __restrict__ dst) {
    int e = blockIdx.x * blockDim.x + threadIdx.x;
    if (e >= N_EDGES) return;
    int d = dst[e];
    int pos = g_rowptr[d] + atomicAdd(&g_degd[d], 1);
    g_csrc[pos] = src[e];
}

// ---------------- GEMM1: p1[n][j] = ns[n] * sum_k feat[n][k] * W1[k][j] ------------
__global__ __launch_bounds__(256, 2)
void gemm1_kernel(const float* __restrict__ feat, const float* __restrict__ W1) {
    __shared__ __align__(16) float ws[HIDDEN * IN_FEATS];  // ws[j*512 + k]
    int tid = threadIdx.x;
    #pragma unroll 4
    for (int idx = tid; idx < HIDDEN * IN_FEATS; idx += 256) {
        int k = idx >> 4, j = idx & 15;       // W1 is [512][16] row-major
        ws[j * IN_FEATS + k] = W1[idx];
    }
    __syncthreads();

    int lane = tid & 31;
    int warp = tid >> 5;
    int row0 = blockIdx.x * 32 + warp * 4;    // 100000 = 3125 * 32

    const float4* f4 = (const float4*)feat;
    const float4* w4 = (const float4*)ws;

    float v[64];
    #pragma unroll
    for (int i = 0; i < 64; i++) v[i] = 0.f;

    #pragma unroll
    for (int i = 0; i < 4; i++) {
        int col = i * 32 + lane;
        float4 a0 = f4[(size_t)(row0 + 0) * 128 + col];
        float4 a1 = f4[(size_t)(row0 + 1) * 128 + col];
        float4 a2 = f4[(size_t)(row0 + 2) * 128 + col];
        float4 a3 = f4[(size_t)(row0 + 3) * 128 + col];
        #pragma unroll
        for (int j = 0; j < 16; j++) {
            float4 w = w4[j * 128 + col];
            v[ 0 + j] = fmaf(a0.x, w.x, fmaf(a0.y, w.y, fmaf(a0.z, w.z, fmaf(a0.w, w.w, v[ 0 + j]))));
            v[16 + j] = fmaf(a1.x, w.x, fmaf(a1.y, w.y, fmaf(a1.z, w.z, fmaf(a1.w, w.w, v[16 + j]))));
            v[32 + j] = fmaf(a2.x, w.x, fmaf(a2.y, w.y, fmaf(a2.z, w.z, fmaf(a2.w, w.w, v[32 + j]))));
            v[48 + j] = fmaf(a3.x, w.x, fmaf(a3.y, w.y, fmaf(a3.z, w.z, fmaf(a3.w, w.w, v[48 + j]))));
        }
    }

    #pragma unroll
    for (int step = 0; step < 5; step++) {
        const int half = 32 >> step;
        const int bit  = 16 >> step;
        bool up = (lane & bit) != 0;
        #pragma unroll
        for (int i = 0; i < half; i++) {
            float send = up ? v[i] : v[i + half];
            float got  = __shfl_xor_sync(0xffffffffu, send, bit);
            v[i] = (up ? v[i + half] : v[i]) + got;
        }
    }
    int id0 = 2 * lane;
    int row = row0 + (id0 >> 4);
    float s = g_ns[row];
    float2 o; o.x = v[0] * s; o.y = v[1] * s;
    *(float2*)(g_p1 + (size_t)row0 * 16 + id0) = o;
}

// ---------------- gather layer 1: q[n] = ns*relu(nd * sum_{e in N(n)} p1[src] + b1) --
// 4 threads per node; each thread owns a float4 feature chunk.
__global__ __launch_bounds__(256)
void gather1_kernel(const float* __restrict__ b1) {
    int g = blockIdx.x * blockDim.x + threadIdx.x;
    int n = g >> 2, c = g & 3;
    if (n >= N_NODES) return;
    int beg = g_rowptr[n], end = g_rowptr[n + 1];
    float4 acc = make_float4(0.f, 0.f, 0.f, 0.f);
    int t = beg;
    for (; t + 1 < end; t += 2) {
        int s0 = g_csrc[t], s1 = g_csrc[t + 1];
        float4 v0 = *(const float4*)(g_p1 + (size_t)s0 * 16 + c * 4);
        float4 v1 = *(const float4*)(g_p1 + (size_t)s1 * 16 + c * 4);
        acc.x += v0.x + v1.x; acc.y += v0.y + v1.y;
        acc.z += v0.z + v1.z; acc.w += v0.w + v1.w;
    }
    if (t < end) {
        int s0 = g_csrc[t];
        float4 v0 = *(const float4*)(g_p1 + (size_t)s0 * 16 + c * 4);
        acc.x += v0.x; acc.y += v0.y; acc.z += v0.z; acc.w += v0.w;
    }
    float ns = g_ns[n], nd = g_nd[n];
    float4 o;
    o.x = ns * fmaxf(fmaf(nd, acc.x, b1[c * 4 + 0]), 0.f);
    o.y = ns * fmaxf(fmaf(nd, acc.y, b1[c * 4 + 1]), 0.f);
    o.z = ns * fmaxf(fmaf(nd, acc.z, b1[c * 4 + 2]), 0.f);
    o.w = ns * fmaxf(fmaf(nd, acc.w, b1[c * 4 + 3]), 0.f);
    ((float4*)g_q)[n * 4 + c] = o;
}

// ---------------- gather layer 2 + final: out[n] = nd*(agg2 @ Wc) + bc ------------
__global__ __launch_bounds__(256)
void gather2_kernel(float* __restrict__ out) {
    int g = blockIdx.x * blockDim.x + threadIdx.x;
    int n = g >> 2, c = g & 3;
    if (n >= N_NODES) return;
    int beg = g_rowptr[n], end = g_rowptr[n + 1];
    float4 acc = make_float4(0.f, 0.f, 0.f, 0.f);
    int t = beg;
    for (; t + 1 < end; t += 2) {
        int s0 = g_csrc[t], s1 = g_csrc[t + 1];
        float4 v0 = *(const float4*)(g_q + (size_t)s0 * 16 + c * 4);
        float4 v1 = *(const float4*)(g_q + (size_t)s1 * 16 + c * 4);
        acc.x += v0.x + v1.x; acc.y += v0.y + v1.y;
        acc.z += v0.z + v1.z; acc.w += v0.w + v1.w;
    }
    if (t < end) {
        int s0 = g_csrc[t];
        float4 v0 = *(const float4*)(g_q + (size_t)s0 * 16 + c * 4);
        acc.x += v0.x; acc.y += v0.y; acc.z += v0.z; acc.w += v0.w;
    }
    // partial projection onto Wc for my 4 dims (o = c*4 .. c*4+3)
    int o0 = c * 4;
    float c0 = acc.x * g_Wc[(o0 + 0) * 3 + 0] + acc.y * g_Wc[(o0 + 1) * 3 + 0]
             + acc.z * g_Wc[(o0 + 2) * 3 + 0] + acc.w * g_Wc[(o0 + 3) * 3 + 0];
    float c1 = acc.x * g_Wc[(o0 + 0) * 3 + 1] + acc.y * g_Wc[(o0 + 1) * 3 + 1]
             + acc.z * g_Wc[(o0 + 2) * 3 + 1] + acc.w * g_Wc[(o0 + 3) * 3 + 1];
    float c2 = acc.x * g_Wc[(o0 + 0) * 3 + 2] + acc.y * g_Wc[(o0 + 1) * 3 + 2]
             + acc.z * g_Wc[(o0 + 2) * 3 + 2] + acc.w * g_Wc[(o0 + 3) * 3 + 2];
    // reduce across the 4 chunk-lanes (consecutive lanes in-warp)
    c0 += __shfl_xor_sync(0xffffffffu, c0, 1);
    c0 += __shfl_xor_sync(0xffffffffu, c0, 2);
    c1 += __shfl_xor_sync(0xffffffffu, c1, 1);
    c1 += __shfl_xor_sync(0xffffffffu, c1, 2);
    c2 += __shfl_xor_sync(0xffffffffu, c2, 1);
    c2 += __shfl_xor_sync(0xffffffffu, c2, 2);
    if (c == 0) {
        float dn = g_nd[n];
        out[n * 3 + 0] = fmaf(dn, c0, g_bc[0]);
        out[n * 3 + 1] = fmaf(dn, c1, g_bc[1]);
        out[n * 3 + 2] = fmaf(dn, c2, g_bc[2]);
    }
}

// ---------------- launch ----------------
extern "C" void kernel_launch(void* const* d_in, const int* in_sizes, int n_in,
                              void* d_out, int out_size) {
    const float* feat = (const float*)d_in[0];
    const int*   src  = (const int*)d_in[1];   // int32 (empirically established)
    const int*   dst  = (const int*)d_in[2];
    const float* W1   = (const float*)d_in[3];
    const float* b1   = (const float*)d_in[4];
    const float* W2   = (const float*)d_in[5];
    const float* b2   = (const float*)d_in[6];
    const float* Wfc  = (const float*)d_in[7];
    const float* bfc  = (const float*)d_in[8];
    float*       out  = (float*)d_out;

    const int TB = 256;
    int zb  = (N_NODES / 4 + TB - 1) / TB;
    int db  = (N_EDGES / 4 + TB - 1) / TB;
    int nwb = (N_NODES + 383) / 384;
    int eb  = (N_EDGES + TB - 1) / TB;
    int gb  = (N_NODES * 4 + TB - 1) / TB;

    zero_kernel   <<<zb, TB>>>();
    deg_kernel    <<<db, TB>>>(src, dst);
    norm_wc_kernel<<<nwb, 384>>>(W2, b2, Wfc, bfc);
    scan1_kernel  <<<N_SCAN_BLKS, SCAN_BLK>>>();
    scan2_kernel  <<<1, 256>>>();
    scan3_kernel  <<<N_SCAN_BLKS, SCAN_BLK>>>();
    permute_kernel<<<eb, TB>>>(src, dst);
    gemm1_kernel  <<<N_NODES / 32, 256>>>(feat, W1);
    gather1_kernel<<<gb, TB>>>(b1);
    gather2_kernel<<<gb, TB>>>(out);
}

// round 10
// speedup vs baseline: 4.1321x; 1.1163x over previous
#include <cuda_runtime.h>
#include <cstdint>

#define N_NODES 100000
#define N_EDGES 3200000
#define IN_FEATS 512
#define HIDDEN 16
#define OUT_FEATS 128
#define N_CLASSES 3

#define SCAN_BLK 512
#define N_SCAN_BLKS ((N_NODES + SCAN_BLK) / SCAN_BLK + 1)

// ---------------- scratch (device globals; touched ONLY from device code) ----------
__device__ __align__(16) float g_p1 [N_NODES * HIDDEN];   // ns * (feat @ W1)
__device__ __align__(16) float g_q  [N_NODES * HIDDEN];   // ns * relu(nd*agg1 + b1)
__device__ __align__(16) float g_ns [N_NODES];
__device__ __align__(16) float g_nd [N_NODES];
__device__ __align__(16) int   g_degs[N_NODES];
__device__ __align__(16) int   g_degd[N_NODES];
__device__ __align__(16) int   g_rowptr[N_NODES + 1];
__device__ __align__(16) int   g_blksum[256];
__device__ __align__(16) int   g_csrc[N_EDGES];
__device__ __align__(16) float g_Wc [HIDDEN * N_CLASSES];
__device__ __align__(16) float g_bc [N_CLASSES];

// ---------------- zero degree arrays ----------------
__global__ void zero_kernel() {
    int i = blockIdx.x * blockDim.x + threadIdx.x;
    if (i < N_NODES / 4) {
        ((int4*)g_degs)[i] = make_int4(0, 0, 0, 0);
        ((int4*)g_degd)[i] = make_int4(0, 0, 0, 0);
    }
}

// ---------------- degree histogram, 4 edges per thread ----------------
__global__ void deg_kernel(const int* __restrict__ src, const int* __restrict__ dst) {
    int t = blockIdx.x * blockDim.x + threadIdx.x;
    if (t >= N_EDGES / 4) return;
    int4 s4 = ((const int4*)src)[t];
    int4 d4 = ((const int4*)dst)[t];
    atomicAdd(&g_degs[s4.x], 1); atomicAdd(&g_degs[s4.y], 1);
    atomicAdd(&g_degs[s4.z], 1); atomicAdd(&g_degs[s4.w], 1);
    atomicAdd(&g_degd[d4.x], 1); atomicAdd(&g_degd[d4.y], 1);
    atomicAdd(&g_degd[d4.z], 1); atomicAdd(&g_degd[d4.w], 1);
}

// ---------------- norms everywhere; block 0 additionally computes Wc, bc ----------
__global__ __launch_bounds__(384)
void norm_wc_kernel(const float* __restrict__ W2, const float* __restrict__ b2,
                    const float* __restrict__ Wfc, const float* __restrict__ bfc) {
    int n = blockIdx.x * 384 + threadIdx.x;
    if (n < N_NODES) {
        g_ns[n] = rsqrtf(fmaxf((float)g_degs[n], 1.0f));
        g_nd[n] = rsqrtf(fmaxf((float)g_degd[n], 1.0f));
    }
    if (blockIdx.x == 0) {
        __shared__ float part[384];
        int t = threadIdx.x;
        int o0 = (t & 7) * 16;
        int idx = t >> 3;                  // 0..47
        int k = idx / N_CLASSES, c = idx % N_CLASSES;
        float s = 0.f;
        #pragma unroll
        for (int o = 0; o < 16; o++)
            s += W2[k * OUT_FEATS + o0 + o] * Wfc[(o0 + o) * N_CLASSES + c];
        part[t] = s;
        __syncthreads();
        if ((t & 7) == 0) {
            float tot = 0.f;
            #pragma unroll
            for (int u = 0; u < 8; u++) tot += part[t + u];
            g_Wc[idx] = tot;
        }
        if (t < N_CLASSES) {
            float s2 = bfc[t];
            for (int o = 0; o < OUT_FEATS; o++)
                s2 += b2[o] * Wfc[o * N_CLASSES + t];
            g_bc[t] = s2;
        }
    }
}

// ---------------- GEMM1 via tf32 MMA: p1[n][j] = ns[n] * (feat @ W1)[n][j] ---------
// Warp = 16 rows (m16), 2 n-tiles of n8, K-loop 64 x k8. A from gmem (cvt.rna),
// W1 tf32-rounded in SMEM. 100000 % 16 == 0 -> warps fully valid or fully skipped.
__device__ __forceinline__ uint32_t f2tf32(float x) {
    uint32_t r;
    asm("cvt.rna.tf32.f32 %0, %1;" : "=r"(r) : "f"(x));
    return r;
}
__device__ __forceinline__ void mma_tf32(float& c0, float& c1, float& c2, float& c3,
                                         uint32_t a0, uint32_t a1, uint32_t a2, uint32_t a3,
                                         uint32_t b0, uint32_t b1) {
    asm volatile("mma.sync.aligned.m16n8k8.row.col.f32.tf32.tf32.f32 "
                 "{%0,%1,%2,%3}, {%4,%5,%6,%7}, {%8,%9}, {%0,%1,%2,%3};"
                 : "+f"(c0), "+f"(c1), "+f"(c2), "+f"(c3)
                 : "r"(a0), "r"(a1), "r"(a2), "r"(a3), "r"(b0), "r"(b1));
}

__global__ __launch_bounds__(256, 2)
void gemm1_kernel(const float* __restrict__ feat, const float* __restrict__ W1) {
    __shared__ __align__(16) uint32_t ws[IN_FEATS * HIDDEN];   // tf32 bits, [k*16+n]
    int tid = threadIdx.x;
    #pragma unroll 8
    for (int i = tid; i < IN_FEATS * HIDDEN; i += 256)
        ws[i] = f2tf32(W1[i]);
    __syncthreads();

    int lane = tid & 31;
    int warp = tid >> 5;
    int r0 = blockIdx.x * 128 + warp * 16;
    if (r0 >= N_NODES) return;              // whole warp invalid (tail block)

    int g = lane >> 2;          // 0..7
    int t = lane & 3;           // 0..3
    int rowA = r0 + g;
    int rowB = rowA + 8;
    const float* fA = feat + (size_t)rowA * IN_FEATS;
    const float* fB = feat + (size_t)rowB * IN_FEATS;

    float c[8];                 // 2 n-tiles x {c0,c1,c2,c3}
    #pragma unroll
    for (int i = 0; i < 8; i++) c[i] = 0.f;

    #pragma unroll 4
    for (int ks = 0; ks < 64; ks++) {
        int k0 = ks * 8;
        uint32_t a0 = f2tf32(fA[k0 + t]);
        uint32_t a1 = f2tf32(fB[k0 + t]);
        uint32_t a2 = f2tf32(fA[k0 + t + 4]);
        uint32_t a3 = f2tf32(fB[k0 + t + 4]);
        // n-tile 0
        uint32_t b0 = ws[(k0 + t) * 16 + g];
        uint32_t b1 = ws[(k0 + t + 4) * 16 + g];
        mma_tf32(c[0], c[1], c[2], c[3], a0, a1, a2, a3, b0, b1);
        // n-tile 1
        uint32_t b2 = ws[(k0 + t) * 16 + 8 + g];
        uint32_t b3 = ws[(k0 + t + 4) * 16 + 8 + g];
        mma_tf32(c[4], c[5], c[6], c[7], a0, a1, a2, a3, b2, b3);
    }

    float sA = g_ns[rowA];
    float sB = g_ns[rowB];
    // c0,c1 -> (rowA, 2t, 2t+1); c2,c3 -> (rowB, 2t, 2t+1); +8 col offset for tile 1
    float2 v;
    v.x = sA * c[0]; v.y = sA * c[1];
    *(float2*)(g_p1 + (size_t)rowA * 16 + 2 * t) = v;
    v.x = sB * c[2]; v.y = sB * c[3];
    *(float2*)(g_p1 + (size_t)rowB * 16 + 2 * t) = v;
    v.x = sA * c[4]; v.y = sA * c[5];
    *(float2*)(g_p1 + (size_t)rowA * 16 + 8 + 2 * t) = v;
    v.x = sB * c[6]; v.y = sB * c[7];
    *(float2*)(g_p1 + (size_t)rowB * 16 + 8 + 2 * t) = v;
}

// ---------------- scan stage 1 ----------------
__global__ __launch_bounds__(SCAN_BLK)
void scan1_kernel() {
    __shared__ int sh[SCAN_BLK];
    int i = blockIdx.x * SCAN_BLK + threadIdx.x;
    int v = (i < N_NODES) ? g_degd[i] : 0;
    sh[threadIdx.x] = v;
    __syncthreads();
    #pragma unroll
    for (int off = 1; off < SCAN_BLK; off <<= 1) {
        int t = (threadIdx.x >= off) ? sh[threadIdx.x - off] : 0;
        __syncthreads();
        sh[threadIdx.x] += t;
        __syncthreads();
    }
    if (i <= N_NODES) g_rowptr[i] = sh[threadIdx.x] - v;
    if (threadIdx.x == SCAN_BLK - 1) g_blksum[blockIdx.x] = sh[SCAN_BLK - 1];
}

// ---------------- scan stage 2 ----------------
__global__ __launch_bounds__(256)
void scan2_kernel() {
    __shared__ int sh[256];
    int t = threadIdx.x;
    int v = (t < N_SCAN_BLKS) ? g_blksum[t] : 0;
    sh[t] = v;
    __syncthreads();
    #pragma unroll
    for (int off = 1; off < 256; off <<= 1) {
        int x = (t >= off) ? sh[t - off] : 0;
        __syncthreads();
        sh[t] += x;
        __syncthreads();
    }
    g_blksum[t] = sh[t] - v;
}

// ---------------- scan stage 3 ----------------
__global__ __launch_bounds__(SCAN_BLK)
void scan3_kernel() {
    int i = blockIdx.x * SCAN_BLK + threadIdx.x;
    if (i <= N_NODES) g_rowptr[i] += g_blksum[blockIdx.x];
    if (i < N_NODES)  g_degd[i] = 0;
}

// ---------------- CSR permute ----------------
__global__ void permute_kernel(const int* __restrict__ src, const int* __restrict__ dst) {
    int e = blockIdx.x * blockDim.x + threadIdx.x;
    if (e >= N_EDGES) return;
    int d = dst[e];
    int pos = g_rowptr[d] + atomicAdd(&g_degd[d], 1);
    g_csrc[pos] = src[e];
}

// ---------------- gather layer 1 ----------------
__global__ __launch_bounds__(256)
void gather1_kernel(const float* __restrict__ b1) {
    int g = blockIdx.x * blockDim.x + threadIdx.x;
    int n = g >> 2, c = g & 3;
    if (n >= N_NODES) return;
    int beg = g_rowptr[n], end = g_rowptr[n + 1];
    float4 acc = make_float4(0.f, 0.f, 0.f, 0.f);
    int t = beg;
    for (; t + 1 < end; t += 2) {
        int s0 = g_csrc[t], s1 = g_csrc[t + 1];
        float4 v0 = *(const float4*)(g_p1 + (size_t)s0 * 16 + c * 4);
        float4 v1 = *(const float4*)(g_p1 + (size_t)s1 * 16 + c * 4);
        acc.x += v0.x + v1.x; acc.y += v0.y + v1.y;
        acc.z += v0.z + v1.z; acc.w += v0.w + v1.w;
    }
    if (t < end) {
        int s0 = g_csrc[t];
        float4 v0 = *(const float4*)(g_p1 + (size_t)s0 * 16 + c * 4);
        acc.x += v0.x; acc.y += v0.y; acc.z += v0.z; acc.w += v0.w;
    }
    float ns = g_ns[n], nd = g_nd[n];
    float4 o;
    o.x = ns * fmaxf(fmaf(nd, acc.x, b1[c * 4 + 0]), 0.f);
    o.y = ns * fmaxf(fmaf(nd, acc.y, b1[c * 4 + 1]), 0.f);
    o.z = ns * fmaxf(fmaf(nd, acc.z, b1[c * 4 + 2]), 0.f);
    o.w = ns * fmaxf(fmaf(nd, acc.w, b1[c * 4 + 3]), 0.f);
    ((float4*)g_q)[n * 4 + c] = o;
}

// ---------------- gather layer 2 + final projection ----------------
__global__ __launch_bounds__(256)
void gather2_kernel(float* __restrict__ out) {
    int g = blockIdx.x * blockDim.x + threadIdx.x;
    int n = g >> 2, c = g & 3;
    if (n >= N_NODES) return;
    int beg = g_rowptr[n], end = g_rowptr[n + 1];
    float4 acc = make_float4(0.f, 0.f, 0.f, 0.f);
    int t = beg;
    for (; t + 1 < end; t += 2) {
        int s0 = g_csrc[t], s1 = g_csrc[t + 1];
        float4 v0 = *(const float4*)(g_q + (size_t)s0 * 16 + c * 4);
        float4 v1 = *(const float4*)(g_q + (size_t)s1 * 16 + c * 4);
        acc.x += v0.x + v1.x; acc.y += v0.y + v1.y;
        acc.z += v0.z + v1.z; acc.w += v0.w + v1.w;
    }
    if (t < end) {
        int s0 = g_csrc[t];
        float4 v0 = *(const float4*)(g_q + (size_t)s0 * 16 + c * 4);
        acc.x += v0.x; acc.y += v0.y; acc.z += v0.z; acc.w += v0.w;
    }
    int o0 = c * 4;
    float c0 = acc.x * g_Wc[(o0 + 0) * 3 + 0] + acc.y * g_Wc[(o0 + 1) * 3 + 0]
             + acc.z * g_Wc[(o0 + 2) * 3 + 0] + acc.w * g_Wc[(o0 + 3) * 3 + 0];
    float c1 = acc.x * g_Wc[(o0 + 0) * 3 + 1] + acc.y * g_Wc[(o0 + 1) * 3 + 1]
             + acc.z * g_Wc[(o0 + 2) * 3 + 1] + acc.w * g_Wc[(o0 + 3) * 3 + 1];
    float c2 = acc.x * g_Wc[(o0 + 0) * 3 + 2] + acc.y * g_Wc[(o0 + 1) * 3 + 2]
             + acc.z * g_Wc[(o0 + 2) * 3 + 2] + acc.w * g_Wc[(o0 + 3) * 3 + 2];
    c0 += __shfl_xor_sync(0xffffffffu, c0, 1);
    c0 += __shfl_xor_sync(0xffffffffu, c0, 2);
    c1 += __shfl_xor_sync(0xffffffffu, c1, 1);
    c1 += __shfl_xor_sync(0xffffffffu, c1, 2);
    c2 += __shfl_xor_sync(0xffffffffu, c2, 1);
    c2 += __shfl_xor_sync(0xffffffffu, c2, 2);
    if (c == 0) {
        float dn = g_nd[n];
        out[n * 3 + 0] = fmaf(dn, c0, g_bc[0]);
        out[n * 3 + 1] = fmaf(dn, c1, g_bc[1]);
        out[n * 3 + 2] = fmaf(dn, c2, g_bc[2]);
    }
}

// ---------------- launch ----------------
extern "C" void kernel_launch(void* const* d_in, const int* in_sizes, int n_in,
                              void* d_out, int out_size) {
    const float* feat = (const float*)d_in[0];
    const int*   src  = (const int*)d_in[1];
    const int*   dst  = (const int*)d_in[2];
    const float* W1   = (const float*)d_in[3];
    const float* b1   = (const float*)d_in[4];
    const float* W2   = (const float*)d_in[5];
    const float* b2   = (const float*)d_in[6];
    const float* Wfc  = (const float*)d_in[7];
    const float* bfc  = (const float*)d_in[8];
    float*       out  = (float*)d_out;

    const int TB = 256;
    int zb  = (N_NODES / 4 + TB - 1) / TB;
    int db  = (N_EDGES / 4 + TB - 1) / TB;
    int nwb = (N_NODES + 383) / 384;
    int eb  = (N_EDGES + TB - 1) / TB;
    int gb  = (N_NODES * 4 + TB - 1) / TB;
    int g1b = (N_NODES + 127) / 128;           // gemm1: 128 rows per CTA

    zero_kernel   <<<zb, TB>>>();
    deg_kernel    <<<db, TB>>>(src, dst);
    norm_wc_kernel<<<nwb, 384>>>(W2, b2, Wfc, bfc);
    gemm1_kernel  <<<g1b, 256>>>(feat, W1);    // launch index 3 -> gets profiled
    scan1_kernel  <<<N_SCAN_BLKS, SCAN_BLK>>>();
    scan2_kernel  <<<1, 256>>>();
    scan3_kernel  <<<N_SCAN_BLKS, SCAN_BLK>>>();
    permute_kernel<<<eb, TB>>>(src, dst);
    gather1_kernel<<<gb, TB>>>(b1);
    gather2_kernel<<<gb, TB>>>(out);
}

// round 11
// speedup vs baseline: 4.3149x; 1.0442x over previous
#include <cuda_runtime.h>
#include <cstdint>

#define N_NODES 100000
#define N_EDGES 3200000
#define IN_FEATS 512
#define HIDDEN 16
#define OUT_FEATS 128
#define N_CLASSES 3

#define SCAN_BLK 512
#define N_SCAN_BLKS ((N_NODES + SCAN_BLK) / SCAN_BLK + 1)

// gemm1 tiling
#define G1_ROWS 128                 // rows per CTA
#define G1_KT   64                  // K-tile width (floats)
#define G1_NKT  (IN_FEATS / G1_KT)  // 8 tiles
#define SA_LD   68                  // 64 + 4 pad (conflict-free)
#define WS_U32  (IN_FEATS * HIDDEN)         // 8192
#define SA_U32  (G1_ROWS * SA_LD)           // 8704
#define G1_SMEM ((WS_U32 + SA_U32) * 4)     // 67584 bytes

// ---------------- scratch (device globals; touched ONLY from device code) ----------
__device__ __align__(16) float g_p1 [N_NODES * HIDDEN];
__device__ __align__(16) float g_q  [N_NODES * HIDDEN];
__device__ __align__(16) float g_ns [N_NODES];
__device__ __align__(16) float g_nd [N_NODES];
__device__ __align__(16) int   g_degs[N_NODES];
__device__ __align__(16) int   g_degd[N_NODES];
__device__ __align__(16) int   g_rowptr[N_NODES + 1];
__device__ __align__(16) int   g_blksum[256];
__device__ __align__(16) int   g_csrc[N_EDGES];
__device__ __align__(16) float g_Wc [HIDDEN * N_CLASSES];
__device__ __align__(16) float g_bc [N_CLASSES];

// ---------------- zero degree arrays ----------------
__global__ void zero_kernel() {
    int i = blockIdx.x * blockDim.x + threadIdx.x;
    if (i < N_NODES / 4) {
        ((int4*)g_degs)[i] = make_int4(0, 0, 0, 0);
        ((int4*)g_degd)[i] = make_int4(0, 0, 0, 0);
    }
}

// ---------------- degree histogram, 4 edges per thread ----------------
__global__ void deg_kernel(const int* __restrict__ src, const int* __restrict__ dst) {
    int t = blockIdx.x * blockDim.x + threadIdx.x;
    if (t >= N_EDGES / 4) return;
    int4 s4 = ((const int4*)src)[t];
    int4 d4 = ((const int4*)dst)[t];
    atomicAdd(&g_degs[s4.x], 1); atomicAdd(&g_degs[s4.y], 1);
    atomicAdd(&g_degs[s4.z], 1); atomicAdd(&g_degs[s4.w], 1);
    atomicAdd(&g_degd[d4.x], 1); atomicAdd(&g_degd[d4.y], 1);
    atomicAdd(&g_degd[d4.z], 1); atomicAdd(&g_degd[d4.w], 1);
}

// ---------------- norms everywhere; block 0 additionally computes Wc, bc ----------
__global__ __launch_bounds__(384)
void norm_wc_kernel(const float* __restrict__ W2, const float* __restrict__ b2,
                    const float* __restrict__ Wfc, const float* __restrict__ bfc) {
    int n = blockIdx.x * 384 + threadIdx.x;
    if (n < N_NODES) {
        g_ns[n] = rsqrtf(fmaxf((float)g_degs[n], 1.0f));
        g_nd[n] = rsqrtf(fmaxf((float)g_degd[n], 1.0f));
    }
    if (blockIdx.x == 0) {
        __shared__ float part[384];
        int t = threadIdx.x;
        int o0 = (t & 7) * 16;
        int idx = t >> 3;                  // 0..47
        int k = idx / N_CLASSES, c = idx % N_CLASSES;
        float s = 0.f;
        #pragma unroll
        for (int o = 0; o < 16; o++)
            s += W2[k * OUT_FEATS + o0 + o] * Wfc[(o0 + o) * N_CLASSES + c];
        part[t] = s;
        __syncthreads();
        if ((t & 7) == 0) {
            float tot = 0.f;
            #pragma unroll
            for (int u = 0; u < 8; u++) tot += part[t + u];
            g_Wc[idx] = tot;
        }
        if (t < N_CLASSES) {
            float s2 = bfc[t];
            for (int o = 0; o < OUT_FEATS; o++)
                s2 += b2[o] * Wfc[o * N_CLASSES + t];
            g_bc[t] = s2;
        }
    }
}

// ---------------- GEMM1 via tf32 MMA, SMEM-staged A tiles -------------------------
__device__ __forceinline__ uint32_t f2tf32(float x) {
    uint32_t r;
    asm("cvt.rna.tf32.f32 %0, %1;" : "=r"(r) : "f"(x));
    return r;
}
__device__ __forceinline__ void mma_tf32(float& c0, float& c1, float& c2, float& c3,
                                         uint32_t a0, uint32_t a1, uint32_t a2, uint32_t a3,
                                         uint32_t b0, uint32_t b1) {
    asm volatile("mma.sync.aligned.m16n8k8.row.col.f32.tf32.tf32.f32 "
                 "{%0,%1,%2,%3}, {%4,%5,%6,%7}, {%8,%9}, {%0,%1,%2,%3};"
                 : "+f"(c0), "+f"(c1), "+f"(c2), "+f"(c3)
                 : "r"(a0), "r"(a1), "r"(a2), "r"(a3), "r"(b0), "r"(b1));
}

__global__ __launch_bounds__(256)
void gemm1_kernel(const float* __restrict__ feat, const float* __restrict__ W1) {
    extern __shared__ __align__(16) uint32_t sm[];
    uint32_t* ws = sm;             // W1 tf32, [k*16 + n]
    uint32_t* SA = sm + WS_U32;    // A tile tf32, [row*68 + k]

    int tid  = threadIdx.x;
    int lane = tid & 31;
    int warp = tid >> 5;
    int g = lane >> 2;             // 0..7
    int t = lane & 3;              // 0..3
    int baseRow = blockIdx.x * G1_ROWS;
    int r0 = baseRow + warp * 16;

    // stage W1 (tf32)
    #pragma unroll 8
    for (int i = tid; i < WS_U32; i += 256)
        ws[i] = f2tf32(W1[i]);

    const float4* f4 = (const float4*)feat;   // 128 float4 per feature row

    // prefetch tile 0:  8 float4 per thread; f = tid + i*256; row=f>>4, c4=f&15
    float4 rbuf[8];
    #pragma unroll
    for (int i = 0; i < 8; i++) {
        int f = tid + i * 256;
        int row = f >> 4, c4 = f & 15;
        int gr = baseRow + row; if (gr >= N_NODES) gr = N_NODES - 1;
        rbuf[i] = f4[(size_t)gr * 128 + c4];   // tile 0: cols 0..63
    }

    float c[8];
    #pragma unroll
    for (int i = 0; i < 8; i++) c[i] = 0.f;

    int arow0 = (warp * 16 + g) * SA_LD;       // SA row offsets for this thread
    int arow1 = (warp * 16 + g + 8) * SA_LD;

    #pragma unroll 1
    for (int kt = 0; kt < G1_NKT; kt++) {
        // store staged tile (cvt to tf32)
        #pragma unroll
        for (int i = 0; i < 8; i++) {
            int f = tid + i * 256;
            int row = f >> 4, c4 = f & 15;
            uint4 u;
            u.x = f2tf32(rbuf[i].x); u.y = f2tf32(rbuf[i].y);
            u.z = f2tf32(rbuf[i].z); u.w = f2tf32(rbuf[i].w);
            *(uint4*)(SA + row * SA_LD + c4 * 4) = u;
        }
        __syncthreads();

        // prefetch next tile
        if (kt + 1 < G1_NKT) {
            #pragma unroll
            for (int i = 0; i < 8; i++) {
                int f = tid + i * 256;
                int row = f >> 4, c4 = f & 15;
                int gr = baseRow + row; if (gr >= N_NODES) gr = N_NODES - 1;
                rbuf[i] = f4[(size_t)gr * 128 + (kt + 1) * 16 + c4];
            }
        }

        // 8 k-steps on this tile
        #pragma unroll
        for (int ks = 0; ks < 8; ks++) {
            int k0 = ks * 8;
            uint32_t a0 = SA[arow0 + k0 + t];
            uint32_t a1 = SA[arow1 + k0 + t];
            uint32_t a2 = SA[arow0 + k0 + t + 4];
            uint32_t a3 = SA[arow1 + k0 + t + 4];
            int kg = kt * G1_KT + k0;
            uint32_t b0 = ws[(kg + t) * 16 + g];
            uint32_t b1 = ws[(kg + t + 4) * 16 + g];
            mma_tf32(c[0], c[1], c[2], c[3], a0, a1, a2, a3, b0, b1);
            uint32_t b2 = ws[(kg + t) * 16 + 8 + g];
            uint32_t b3 = ws[(kg + t + 4) * 16 + 8 + g];
            mma_tf32(c[4], c[5], c[6], c[7], a0, a1, a2, a3, b2, b3);
        }
        __syncthreads();
    }

    if (r0 < N_NODES) {        // N_NODES % 16 == 0 -> whole warp-tile valid
        int rowA = r0 + g;
        int rowB = rowA + 8;
        float sA = g_ns[rowA];
        float sB = g_ns[rowB];
        float2 v;
        v.x = sA * c[0]; v.y = sA * c[1];
        *(float2*)(g_p1 + (size_t)rowA * 16 + 2 * t) = v;
        v.x = sB * c[2]; v.y = sB * c[3];
        *(float2*)(g_p1 + (size_t)rowB * 16 + 2 * t) = v;
        v.x = sA * c[4]; v.y = sA * c[5];
        *(float2*)(g_p1 + (size_t)rowA * 16 + 8 + 2 * t) = v;
        v.x = sB * c[6]; v.y = sB * c[7];
        *(float2*)(g_p1 + (size_t)rowB * 16 + 8 + 2 * t) = v;
    }
}

// ---------------- scan stage 1 ----------------
__global__ __launch_bounds__(SCAN_BLK)
void scan1_kernel() {
    __shared__ int sh[SCAN_BLK];
    int i = blockIdx.x * SCAN_BLK + threadIdx.x;
    int v = (i < N_NODES) ? g_degd[i] : 0;
    sh[threadIdx.x] = v;
    __syncthreads();
    #pragma unroll
    for (int off = 1; off < SCAN_BLK; off <<= 1) {
        int t = (threadIdx.x >= off) ? sh[threadIdx.x - off] : 0;
        __syncthreads();
        sh[threadIdx.x] += t;
        __syncthreads();
    }
    if (i <= N_NODES) g_rowptr[i] = sh[threadIdx.x] - v;
    if (threadIdx.x == SCAN_BLK - 1) g_blksum[blockIdx.x] = sh[SCAN_BLK - 1];
}

// ---------------- scan stage 2 ----------------
__global__ __launch_bounds__(256)
void scan2_kernel() {
    __shared__ int sh[256];
    int t = threadIdx.x;
    int v = (t < N_SCAN_BLKS) ? g_blksum[t] : 0;
    sh[t] = v;
    __syncthreads();
    #pragma unroll
    for (int off = 1; off < 256; off <<= 1) {
        int x = (t >= off) ? sh[t - off] : 0;
        __syncthreads();
        sh[t] += x;
        __syncthreads();
    }
    g_blksum[t] = sh[t] - v;
}

// ---------------- scan stage 3 ----------------
__global__ __launch_bounds__(SCAN_BLK)
void scan3_kernel() {
    int i = blockIdx.x * SCAN_BLK + threadIdx.x;
    if (i <= N_NODES) g_rowptr[i] += g_blksum[blockIdx.x];
    if (i < N_NODES)  g_degd[i] = 0;
}

// ---------------- CSR permute ----------------
__global__ void permute_kernel(const int* __restrict__ src, const int* __restrict__ dst) {
    int e = blockIdx.x * blockDim.x + threadIdx.x;
    if (e >= N_EDGES) return;
    int d = dst[e];
    int pos = g_rowptr[d] + atomicAdd(&g_degd[d], 1);
    g_csrc[pos] = src[e];
}

// ---------------- gather layer 1 ----------------
__global__ __launch_bounds__(256)
void gather1_kernel(const float* __restrict__ b1) {
    int g = blockIdx.x * blockDim.x + threadIdx.x;
    int n = g >> 2, c = g & 3;
    if (n >= N_NODES) return;
    int beg = g_rowptr[n], end = g_rowptr[n + 1];
    float4 acc = make_float4(0.f, 0.f, 0.f, 0.f);
    int t = beg;
    for (; t + 1 < end; t += 2) {
        int s0 = g_csrc[t], s1 = g_csrc[t + 1];
        float4 v0 = *(const float4*)(g_p1 + (size_t)s0 * 16 + c * 4);
        float4 v1 = *(const float4*)(g_p1 + (size_t)s1 * 16 + c * 4);
        acc.x += v0.x + v1.x; acc.y += v0.y + v1.y;
        acc.z += v0.z + v1.z; acc.w += v0.w + v1.w;
    }
    if (t < end) {
        int s0 = g_csrc[t];
        float4 v0 = *(const float4*)(g_p1 + (size_t)s0 * 16 + c * 4);
        acc.x += v0.x; acc.y += v0.y; acc.z += v0.z; acc.w += v0.w;
    }
    float ns = g_ns[n], nd = g_nd[n];
    float4 o;
    o.x = ns * fmaxf(fmaf(nd, acc.x, b1[c * 4 + 0]), 0.f);
    o.y = ns * fmaxf(fmaf(nd, acc.y, b1[c * 4 + 1]), 0.f);
    o.z = ns * fmaxf(fmaf(nd, acc.z, b1[c * 4 + 2]), 0.f);
    o.w = ns * fmaxf(fmaf(nd, acc.w, b1[c * 4 + 3]), 0.f);
    ((float4*)g_q)[n * 4 + c] = o;
}

// ---------------- gather layer 2 + final projection ----------------
__global__ __launch_bounds__(256)
void gather2_kernel(float* __restrict__ out) {
    int g = blockIdx.x * blockDim.x + threadIdx.x;
    int n = g >> 2, c = g & 3;
    if (n >= N_NODES) return;
    int beg = g_rowptr[n], end = g_rowptr[n + 1];
    float4 acc = make_float4(0.f, 0.f, 0.f, 0.f);
    int t = beg;
    for (; t + 1 < end; t += 2) {
        int s0 = g_csrc[t], s1 = g_csrc[t + 1];
        float4 v0 = *(const float4*)(g_q + (size_t)s0 * 16 + c * 4);
        float4 v1 = *(const float4*)(g_q + (size_t)s1 * 16 + c * 4);
        acc.x += v0.x + v1.x; acc.y += v0.y + v1.y;
        acc.z += v0.z + v1.z; acc.w += v0.w + v1.w;
    }
    if (t < end) {
        int s0 = g_csrc[t];
        float4 v0 = *(const float4*)(g_q + (size_t)s0 * 16 + c * 4);
        acc.x += v0.x; acc.y += v0.y; acc.z += v0.z; acc.w += v0.w;
    }
    int o0 = c * 4;
    float c0 = acc.x * g_Wc[(o0 + 0) * 3 + 0] + acc.y * g_Wc[(o0 + 1) * 3 + 0]
             + acc.z * g_Wc[(o0 + 2) * 3 + 0] + acc.w * g_Wc[(o0 + 3) * 3 + 0];
    float c1 = acc.x * g_Wc[(o0 + 0) * 3 + 1] + acc.y * g_Wc[(o0 + 1) * 3 + 1]
             + acc.z * g_Wc[(o0 + 2) * 3 + 1] + acc.w * g_Wc[(o0 + 3) * 3 + 1];
    float c2 = acc.x * g_Wc[(o0 + 0) * 3 + 2] + acc.y * g_Wc[(o0 + 1) * 3 + 2]
             + acc.z * g_Wc[(o0 + 2) * 3 + 2] + acc.w * g_Wc[(o0 + 3) * 3 + 2];
    c0 += __shfl_xor_sync(0xffffffffu, c0, 1);
    c0 += __shfl_xor_sync(0xffffffffu, c0, 2);
    c1 += __shfl_xor_sync(0xffffffffu, c1, 1);
    c1 += __shfl_xor_sync(0xffffffffu, c1, 2);
    c2 += __shfl_xor_sync(0xffffffffu, c2, 1);
    c2 += __shfl_xor_sync(0xffffffffu, c2, 2);
    if (c == 0) {
        float dn = g_nd[n];
        out[n * 3 + 0] = fmaf(dn, c0, g_bc[0]);
        out[n * 3 + 1] = fmaf(dn, c1, g_bc[1]);
        out[n * 3 + 2] = fmaf(dn, c2, g_bc[2]);
    }
}

// ---------------- launch ----------------
extern "C" void kernel_launch(void* const* d_in, const int* in_sizes, int n_in,
                              void* d_out, int out_size) {
    const float* feat = (const float*)d_in[0];
    const int*   src  = (const int*)d_in[1];
    const int*   dst  = (const int*)d_in[2];
    const float* W1   = (const float*)d_in[3];
    const float* b1   = (const float*)d_in[4];
    const float* W2   = (const float*)d_in[5];
    const float* b2   = (const float*)d_in[6];
    const float* Wfc  = (const float*)d_in[7];
    const float* bfc  = (const float*)d_in[8];
    float*       out  = (float*)d_out;

    static int smem_set = 0;
    if (!smem_set) {
        cudaFuncSetAttribute(gemm1_kernel,
                             cudaFuncAttributeMaxDynamicSharedMemorySize, G1_SMEM);
        smem_set = 1;
    }

    const int TB = 256;
    int zb  = (N_NODES / 4 + TB - 1) / TB;
    int db  = (N_EDGES / 4 + TB - 1) / TB;
    int nwb = (N_NODES + 383) / 384;
    int eb  = (N_EDGES + TB - 1) / TB;
    int gb  = (N_NODES * 4 + TB - 1) / TB;
    int g1b = (N_NODES + G1_ROWS - 1) / G1_ROWS;   // 782

    zero_kernel   <<<zb, TB>>>();
    deg_kernel    <<<db, TB>>>(src, dst);
    norm_wc_kernel<<<nwb, 384>>>(W2, b2, Wfc, bfc);
    gemm1_kernel  <<<g1b, 256, G1_SMEM>>>(feat, W1);   // index 3 -> profiled
    scan1_kernel  <<<N_SCAN_BLKS, SCAN_BLK>>>();
    scan2_kernel  <<<1, 256>>>();
    scan3_kernel  <<<N_SCAN_BLKS, SCAN_BLK>>>();
    permute_kernel<<<eb, TB>>>(src, dst);
    gather1_kernel<<<gb, TB>>>(b1);
    gather2_kernel<<<gb, TB>>>(out);
}

// round 14
// speedup vs baseline: 4.3526x; 1.0087x over previous
#include <cuda_runtime.h>
#include <cstdint>

#define N_NODES 100000
#define N_EDGES 3200000
#define IN_FEATS 512
#define HIDDEN 16
#define OUT_FEATS 128
#define N_CLASSES 3

#define SCAN_BLK 512
#define N_SCAN_BLKS ((N_NODES + SCAN_BLK) / SCAN_BLK + 1)

// gemm1 tiling: 128 rows/CTA, K-tiles of 32, double-buffered cp.async
#define G1_ROWS 128
#define G1_KT   32
#define G1_NKT  (IN_FEATS / G1_KT)   // 16
#define SA_LD   36                   // 32 + 4 pad words

// ---------------- scratch (device globals; touched ONLY from device code) ----------
__device__ __align__(16) float    g_p1 [N_NODES * HIDDEN];
__device__ __align__(16) float    g_q  [N_NODES * HIDDEN];
__device__ __align__(16) float    g_ns [N_NODES];
__device__ __align__(16) float    g_nd [N_NODES];
__device__ __align__(16) int      g_degs[N_NODES];
__device__ __align__(16) int      g_degd[N_NODES];
__device__ __align__(16) int      g_rowptr[N_NODES + 1];
__device__ __align__(16) int      g_blksum[256];
__device__ __align__(16) int      g_csrc[N_EDGES];
__device__ __align__(16) uint32_t g_w1t[IN_FEATS * HIDDEN];   // W1 as tf32 bits
__device__ __align__(16) float    g_Wc [HIDDEN * N_CLASSES];
__device__ __align__(16) float    g_bc [N_CLASSES];

__device__ __forceinline__ uint32_t f2tf32(float x) {
    uint32_t r;
    asm("cvt.rna.tf32.f32 %0, %1;" : "=r"(r) : "f"(x));
    return r;
}
__device__ __forceinline__ uint32_t bits2tf32(uint32_t xb) {
    uint32_t r;
    asm("cvt.rna.tf32.f32 %0, %1;" : "=r"(r) : "f"(__uint_as_float(xb)));
    return r;
}

// ---------------- zero degrees + build tf32 W1 ----------------
__global__ void zero_kernel(const float* __restrict__ W1) {
    int i = blockIdx.x * blockDim.x + threadIdx.x;
    if (i < N_NODES / 4) {
        ((int4*)g_degs)[i] = make_int4(0, 0, 0, 0);
        ((int4*)g_degd)[i] = make_int4(0, 0, 0, 0);
    }
    if (i < IN_FEATS * HIDDEN)
        g_w1t[i] = f2tf32(W1[i]);
}

// ---------------- degree histogram, 4 edges per thread ----------------
__global__ void deg_kernel(const int* __restrict__ src, const int* __restrict__ dst) {
    int t = blockIdx.x * blockDim.x + threadIdx.x;
    if (t >= N_EDGES / 4) return;
    int4 s4 = ((const int4*)src)[t];
    int4 d4 = ((const int4*)dst)[t];
    atomicAdd(&g_degs[s4.x], 1); atomicAdd(&g_degs[s4.y], 1);
    atomicAdd(&g_degs[s4.z], 1); atomicAdd(&g_degs[s4.w], 1);
    atomicAdd(&g_degd[d4.x], 1); atomicAdd(&g_degd[d4.y], 1);
    atomicAdd(&g_degd[d4.z], 1); atomicAdd(&g_degd[d4.w], 1);
}

// ---------------- norms everywhere; block 0 additionally computes Wc, bc ----------
__global__ __launch_bounds__(384)
void norm_wc_kernel(const float* __restrict__ W2, const float* __restrict__ b2,
                    const float* __restrict__ Wfc, const float* __restrict__ bfc) {
    int n = blockIdx.x * 384 + threadIdx.x;
    if (n < N_NODES) {
        g_ns[n] = rsqrtf(fmaxf((float)g_degs[n], 1.0f));
        g_nd[n] = rsqrtf(fmaxf((float)g_degd[n], 1.0f));
    }
    if (blockIdx.x == 0) {
        __shared__ float part[384];
        int t = threadIdx.x;
        int o0 = (t & 7) * 16;
        int idx = t >> 3;
        int k = idx / N_CLASSES, c = idx % N_CLASSES;
        float s = 0.f;
        #pragma unroll
        for (int o = 0; o < 16; o++)
            s += W2[k * OUT_FEATS + o0 + o] * Wfc[(o0 + o) * N_CLASSES + c];
        part[t] = s;
        __syncthreads();
        if ((t & 7) == 0) {
            float tot = 0.f;
            #pragma unroll
            for (int u = 0; u < 8; u++) tot += part[t + u];
            g_Wc[idx] = tot;
        }
        if (t < N_CLASSES) {
            float s2 = bfc[t];
            for (int o = 0; o < OUT_FEATS; o++)
                s2 += b2[o] * Wfc[o * N_CLASSES + t];
            g_bc[t] = s2;
        }
    }
}

// ---------------- GEMM1: tf32 MMA + cp.async double-buffered tiles ----------------
__device__ __forceinline__ void mma_tf32(float& c0, float& c1, float& c2, float& c3,
                                         uint32_t a0, uint32_t a1, uint32_t a2, uint32_t a3,
                                         uint32_t b0, uint32_t b1) {
    asm volatile("mma.sync.aligned.m16n8k8.row.col.f32.tf32.tf32.f32 "
                 "{%0,%1,%2,%3}, {%4,%5,%6,%7}, {%8,%9}, {%0,%1,%2,%3};"
                 : "+f"(c0), "+f"(c1), "+f"(c2), "+f"(c3)
                 : "r"(a0), "r"(a1), "r"(a2), "r"(a3), "r"(b0), "r"(b1));
}
__device__ __forceinline__ void cp16(uint32_t smem_addr, const void* gptr) {
    asm volatile("cp.async.ca.shared.global [%0], [%1], 16;"
                 :: "r"(smem_addr), "l"(gptr));
}

__global__ __launch_bounds__(256, 5)
void gemm1_kernel(const float* __restrict__ feat) {
    __shared__ __align__(16) uint32_t SA[2][G1_ROWS * SA_LD];  // raw fp32 bits
    __shared__ __align__(16) uint32_t SW[2][G1_KT * HIDDEN];   // tf32 bits

    int tid  = threadIdx.x;
    int lane = tid & 31;
    int warp = tid >> 5;
    int g = lane >> 2;
    int t = lane & 3;
    int baseRow = blockIdx.x * G1_ROWS;
    int r0 = baseRow + warp * 16;

    uint32_t saBase[2], swBase[2];
    saBase[0] = (uint32_t)__cvta_generic_to_shared(SA[0]);
    saBase[1] = (uint32_t)__cvta_generic_to_shared(SA[1]);
    swBase[0] = (uint32_t)__cvta_generic_to_shared(SW[0]);
    swBase[1] = (uint32_t)__cvta_generic_to_shared(SW[1]);

    auto issue = [&](int kt, int buf) {
        #pragma unroll
        for (int i = 0; i < 4; i++) {
            int f = tid + i * 256;         // 1024 chunks: 128 rows x 8 chunks
            int row = f >> 3, c = f & 7;
            int gr = baseRow + row; if (gr >= N_NODES) gr = N_NODES - 1;
            cp16(saBase[buf] + (row * SA_LD + c * 4) * 4,
                 feat + (size_t)gr * IN_FEATS + kt * G1_KT + c * 4);
        }
        if (tid < 128) {                   // W tile: 32x16 words = 128 chunks
            int row = tid >> 2, c = tid & 3;
            cp16(swBase[buf] + (row * HIDDEN + c * 4) * 4,
                 g_w1t + (kt * G1_KT + row) * HIDDEN + c * 4);
        }
        asm volatile("cp.async.commit_group;");
    };

    issue(0, 0);
    issue(1, 1);

    float c[8];
    #pragma unroll
    for (int i = 0; i < 8; i++) c[i] = 0.f;

    int arow0 = (warp * 16 + g) * SA_LD;
    int arow1 = (warp * 16 + g + 8) * SA_LD;

    #pragma unroll 1
    for (int kt = 0; kt < G1_NKT; kt++) {
        int buf = kt & 1;
        // Group accounting: at kt the most recent commit is group kt+1 (for
        // kt <= G1_NKT-2), so wait_group 1 covers group kt. At the FINAL
        // iteration the most recent commit IS group kt -> need wait_group 0.
        if (kt == G1_NKT - 1)
            asm volatile("cp.async.wait_group 0;");
        else
            asm volatile("cp.async.wait_group 1;");
        __syncthreads();

        #pragma unroll
        for (int ks = 0; ks < 4; ks++) {
            int k0 = ks * 8;
            uint32_t a0 = bits2tf32(SA[buf][arow0 + k0 + t]);
            uint32_t a1 = bits2tf32(SA[buf][arow1 + k0 + t]);
            uint32_t a2 = bits2tf32(SA[buf][arow0 + k0 + t + 4]);
            uint32_t a3 = bits2tf32(SA[buf][arow1 + k0 + t + 4]);
            uint32_t b0 = SW[buf][(k0 + t) * 16 + g];
            uint32_t b1 = SW[buf][(k0 + t + 4) * 16 + g];
            mma_tf32(c[0], c[1], c[2], c[3], a0, a1, a2, a3, b0, b1);
            uint32_t b2 = SW[buf][(k0 + t) * 16 + 8 + g];
            uint32_t b3 = SW[buf][(k0 + t + 4) * 16 + 8 + g];
            mma_tf32(c[4], c[5], c[6], c[7], a0, a1, a2, a3, b2, b3);
        }
        __syncthreads();
        if (kt + 2 < G1_NKT) issue(kt + 2, buf);
    }

    if (r0 < N_NODES) {       // N_NODES % 16 == 0 -> full warp-tile valid
        int rowA = r0 + g;
        int rowB = rowA + 8;
        float sA = g_ns[rowA];
        float sB = g_ns[rowB];
        float2 v;
        v.x = sA * c[0]; v.y = sA * c[1];
        *(float2*)(g_p1 + (size_t)rowA * 16 + 2 * t) = v;
        v.x = sB * c[2]; v.y = sB * c[3];
        *(float2*)(g_p1 + (size_t)rowB * 16 + 2 * t) = v;
        v.x = sA * c[4]; v.y = sA * c[5];
        *(float2*)(g_p1 + (size_t)rowA * 16 + 8 + 2 * t) = v;
        v.x = sB * c[6]; v.y = sB * c[7];
        *(float2*)(g_p1 + (size_t)rowB * 16 + 8 + 2 * t) = v;
    }
}

// ---------------- scan stage 1 ----------------
__global__ __launch_bounds__(SCAN_BLK)
void scan1_kernel() {
    __shared__ int sh[SCAN_BLK];
    int i = blockIdx.x * SCAN_BLK + threadIdx.x;
    int v = (i < N_NODES) ? g_degd[i] : 0;
    sh[threadIdx.x] = v;
    __syncthreads();
    #pragma unroll
    for (int off = 1; off < SCAN_BLK; off <<= 1) {
        int t = (threadIdx.x >= off) ? sh[threadIdx.x - off] : 0;
        __syncthreads();
        sh[threadIdx.x] += t;
        __syncthreads();
    }
    if (i <= N_NODES) g_rowptr[i] = sh[threadIdx.x] - v;
    if (threadIdx.x == SCAN_BLK - 1) g_blksum[blockIdx.x] = sh[SCAN_BLK - 1];
}

// ---------------- scan stage 2 ----------------
__global__ __launch_bounds__(256)
void scan2_kernel() {
    __shared__ int sh[256];
    int t = threadIdx.x;
    int v = (t < N_SCAN_BLKS) ? g_blksum[t] : 0;
    sh[t] = v;
    __syncthreads();
    #pragma unroll
    for (int off = 1; off < 256; off <<= 1) {
        int x = (t >= off) ? sh[t - off] : 0;
        __syncthreads();
        sh[t] += x;
        __syncthreads();
    }
    g_blksum[t] = sh[t] - v;
}

// ---------------- scan stage 3 ----------------
__global__ __launch_bounds__(SCAN_BLK)
void scan3_kernel() {
    int i = blockIdx.x * SCAN_BLK + threadIdx.x;
    if (i <= N_NODES) g_rowptr[i] += g_blksum[blockIdx.x];
    if (i < N_NODES)  g_degd[i] = 0;
}

// ---------------- CSR permute ----------------
__global__ void permute_kernel(const int* __restrict__ src, const int* __restrict__ dst) {
    int e = blockIdx.x * blockDim.x + threadIdx.x;
    if (e >= N_EDGES) return;
    int d = dst[e];
    int pos = g_rowptr[d] + atomicAdd(&g_degd[d], 1);
    g_csrc[pos] = src[e];
}

// ---------------- gather layer 1 ----------------
__global__ __launch_bounds__(256)
void gather1_kernel(const float* __restrict__ b1) {
    int g = blockIdx.x * blockDim.x + threadIdx.x;
    int n = g >> 2, c = g & 3;
    if (n >= N_NODES) return;
    int beg = g_rowptr[n], end = g_rowptr[n + 1];
    float4 acc = make_float4(0.f, 0.f, 0.f, 0.f);
    int t = beg;
    for (; t + 1 < end; t += 2) {
        int s0 = g_csrc[t], s1 = g_csrc[t + 1];
        float4 v0 = *(const float4*)(g_p1 + (size_t)s0 * 16 + c * 4);
        float4 v1 = *(const float4*)(g_p1 + (size_t)s1 * 16 + c * 4);
        acc.x += v0.x + v1.x; acc.y += v0.y + v1.y;
        acc.z += v0.z + v1.z; acc.w += v0.w + v1.w;
    }
    if (t < end) {
        int s0 = g_csrc[t];
        float4 v0 = *(const float4*)(g_p1 + (size_t)s0 * 16 + c * 4);
        acc.x += v0.x; acc.y += v0.y; acc.z += v0.z; acc.w += v0.w;
    }
    float ns = g_ns[n], nd = g_nd[n];
    float4 o;
    o.x = ns * fmaxf(fmaf(nd, acc.x, b1[c * 4 + 0]), 0.f);
    o.y = ns * fmaxf(fmaf(nd, acc.y, b1[c * 4 + 1]), 0.f);
    o.z = ns * fmaxf(fmaf(nd, acc.z, b1[c * 4 + 2]), 0.f);
    o.w = ns * fmaxf(fmaf(nd, acc.w, b1[c * 4 + 3]), 0.f);
    ((float4*)g_q)[n * 4 + c] = o;
}

// ---------------- gather layer 2 + final projection ----------------
__global__ __launch_bounds__(256)
void gather2_kernel(float* __restrict__ out) {
    int g = blockIdx.x * blockDim.x + threadIdx.x;
    int n = g >> 2, c = g & 3;
    if (n >= N_NODES) return;
    int beg = g_rowptr[n], end = g_rowptr[n + 1];
    float4 acc = make_float4(0.f, 0.f, 0.f, 0.f);
    int t = beg;
    for (; t + 1 < end; t += 2) {
        int s0 = g_csrc[t], s1 = g_csrc[t + 1];
        float4 v0 = *(const float4*)(g_q + (size_t)s0 * 16 + c * 4);
        float4 v1 = *(const float4*)(g_q + (size_t)s1 * 16 + c * 4);
        acc.x += v0.x + v1.x; acc.y += v0.y + v1.y;
        acc.z += v0.z + v1.z; acc.w += v0.w + v1.w;
    }
    if (t < end) {
        int s0 = g_csrc[t];
        float4 v0 = *(const float4*)(g_q + (size_t)s0 * 16 + c * 4);
        acc.x += v0.x; acc.y += v0.y; acc.z += v0.z; acc.w += v0.w;
    }
    int o0 = c * 4;
    float c0 = acc.x * g_Wc[(o0 + 0) * 3 + 0] + acc.y * g_Wc[(o0 + 1) * 3 + 0]
             + acc.z * g_Wc[(o0 + 2) * 3 + 0] + acc.w * g_Wc[(o0 + 3) * 3 + 0];
    float c1 = acc.x * g_Wc[(o0 + 0) * 3 + 1] + acc.y * g_Wc[(o0 + 1) * 3 + 1]
             + acc.z * g_Wc[(o0 + 2) * 3 + 1] + acc.w * g_Wc[(o0 + 3) * 3 + 1];
    float c2 = acc.x * g_Wc[(o0 + 0) * 3 + 2] + acc.y * g_Wc[(o0 + 1) * 3 + 2]
             + acc.z * g_Wc[(o0 + 2) * 3 + 2] + acc.w * g_Wc[(o0 + 3) * 3 + 2];
    c0 += __shfl_xor_sync(0xffffffffu, c0, 1);
    c0 += __shfl_xor_sync(0xffffffffu, c0, 2);
    c1 += __shfl_xor_sync(0xffffffffu, c1, 1);
    c1 += __shfl_xor_sync(0xffffffffu, c1, 2);
    c2 += __shfl_xor_sync(0xffffffffu, c2, 1);
    c2 += __shfl_xor_sync(0xffffffffu, c2, 2);
    if (c == 0) {
        float dn = g_nd[n];
        out[n * 3 + 0] = fmaf(dn, c0, g_bc[0]);
        out[n * 3 + 1] = fmaf(dn, c1, g_bc[1]);
        out[n * 3 + 2] = fmaf(dn, c2, g_bc[2]);
    }
}

// ---------------- launch ----------------
extern "C" void kernel_launch(void* const* d_in, const int* in_sizes, int n_in,
                              void* d_out, int out_size) {
    const float* feat = (const float*)d_in[0];
    const int*   src  = (const int*)d_in[1];
    const int*   dst  = (const int*)d_in[2];
    const float* W1   = (const float*)d_in[3];
    const float* b1   = (const float*)d_in[4];
    const float* W2   = (const float*)d_in[5];
    const float* b2   = (const float*)d_in[6];
    const float* Wfc  = (const float*)d_in[7];
    const float* bfc  = (const float*)d_in[8];
    float*       out  = (float*)d_out;

    const int TB = 256;
    int zb  = (IN_FEATS * HIDDEN + TB - 1) / TB;
    if (zb < (N_NODES / 4 + TB - 1) / TB) zb = (N_NODES / 4 + TB - 1) / TB;
    int db  = (N_EDGES / 4 + TB - 1) / TB;
    int nwb = (N_NODES + 383) / 384;
    int eb  = (N_EDGES + TB - 1) / TB;
    int gb  = (N_NODES * 4 + TB - 1) / TB;
    int g1b = (N_NODES + G1_ROWS - 1) / G1_ROWS;   // 782

    zero_kernel   <<<zb, TB>>>(W1);
    deg_kernel    <<<db, TB>>>(src, dst);
    norm_wc_kernel<<<nwb, 384>>>(W2, b2, Wfc, bfc);
    gemm1_kernel  <<<g1b, 256>>>(feat);            // index 3 -> profiled
    scan1_kernel  <<<N_SCAN_BLKS, SCAN_BLK>>>();
    scan2_kernel  <<<1, 256>>>();
    scan3_kernel  <<<N_SCAN_BLKS, SCAN_BLK>>>();
    permute_kernel<<<eb, TB>>>(src, dst);
    gather1_kernel<<<gb, TB>>>(b1);
    gather2_kernel<<<gb, TB>>>(out);
}

// round 15
// speedup vs baseline: 4.6200x; 1.0614x over previous
#include <cuda_runtime.h>
#include <cstdint>

#define N_NODES 100000
#define N_EDGES 3200000
#define IN_FEATS 512
#define HIDDEN 16
#define OUT_FEATS 128
#define N_CLASSES 3

#define SCAN_BLK 512
#define N_SCAN_BLKS ((N_NODES + SCAN_BLK) / SCAN_BLK + 1)

// gemm1: 128 rows/CTA; per-warp 16-row tile; K-tiles of 32, per-warp double buffer
#define G1_ROWS 128
#define G1_KT   32
#define G1_NKT  (IN_FEATS / G1_KT)   // 16
#define SA_LD   36                   // 32 + 4 pad words (conflict-free)
#define SA_STG  (16 * SA_LD)         // 576 words per warp-stage

// ---------------- scratch (device globals; touched ONLY from device code) ----------
__device__ __align__(16) float    g_p1 [N_NODES * HIDDEN];
__device__ __align__(16) float    g_q  [N_NODES * HIDDEN];
__device__ __align__(16) float    g_ns [N_NODES];
__device__ __align__(16) float    g_nd [N_NODES];
__device__ __align__(16) int      g_degs[N_NODES];
__device__ __align__(16) int      g_degd[N_NODES];
__device__ __align__(16) int      g_rowptr[N_NODES + 1];
__device__ __align__(16) int      g_blksum[256];
__device__ __align__(16) int      g_csrc[N_EDGES];
__device__ __align__(16) uint32_t g_w1t[IN_FEATS * HIDDEN];   // W1 as tf32 bits
__device__ __align__(16) float    g_Wc [HIDDEN * N_CLASSES];
__device__ __align__(16) float    g_bc [N_CLASSES];

__device__ __forceinline__ uint32_t f2tf32(float x) {
    uint32_t r;
    asm("cvt.rna.tf32.f32 %0, %1;" : "=r"(r) : "f"(x));
    return r;
}
__device__ __forceinline__ uint32_t bits2tf32(uint32_t xb) {
    uint32_t r;
    asm("cvt.rna.tf32.f32 %0, %1;" : "=r"(r) : "f"(__uint_as_float(xb)));
    return r;
}

// ---------------- zero degrees + build tf32 W1 ----------------
__global__ void zero_kernel(const float* __restrict__ W1) {
    int i = blockIdx.x * blockDim.x + threadIdx.x;
    if (i < N_NODES / 4) {
        ((int4*)g_degs)[i] = make_int4(0, 0, 0, 0);
        ((int4*)g_degd)[i] = make_int4(0, 0, 0, 0);
    }
    if (i < IN_FEATS * HIDDEN)
        g_w1t[i] = f2tf32(W1[i]);
}

// ---------------- degree histogram, 4 edges per thread ----------------
__global__ void deg_kernel(const int* __restrict__ src, const int* __restrict__ dst) {
    int t = blockIdx.x * blockDim.x + threadIdx.x;
    if (t >= N_EDGES / 4) return;
    int4 s4 = ((const int4*)src)[t];
    int4 d4 = ((const int4*)dst)[t];
    atomicAdd(&g_degs[s4.x], 1); atomicAdd(&g_degs[s4.y], 1);
    atomicAdd(&g_degs[s4.z], 1); atomicAdd(&g_degs[s4.w], 1);
    atomicAdd(&g_degd[d4.x], 1); atomicAdd(&g_degd[d4.y], 1);
    atomicAdd(&g_degd[d4.z], 1); atomicAdd(&g_degd[d4.w], 1);
}

// ---------------- norms everywhere; block 0 additionally computes Wc, bc ----------
__global__ __launch_bounds__(384)
void norm_wc_kernel(const float* __restrict__ W2, const float* __restrict__ b2,
                    const float* __restrict__ Wfc, const float* __restrict__ bfc) {
    int n = blockIdx.x * 384 + threadIdx.x;
    if (n < N_NODES) {
        g_ns[n] = rsqrtf(fmaxf((float)g_degs[n], 1.0f));
        g_nd[n] = rsqrtf(fmaxf((float)g_degd[n], 1.0f));
    }
    if (blockIdx.x == 0) {
        __shared__ float part[384];
        int t = threadIdx.x;
        int o0 = (t & 7) * 16;
        int idx = t >> 3;
        int k = idx / N_CLASSES, c = idx % N_CLASSES;
        float s = 0.f;
        #pragma unroll
        for (int o = 0; o < 16; o++)
            s += W2[k * OUT_FEATS + o0 + o] * Wfc[(o0 + o) * N_CLASSES + c];
        part[t] = s;
        __syncthreads();
        if ((t & 7) == 0) {
            float tot = 0.f;
            #pragma unroll
            for (int u = 0; u < 8; u++) tot += part[t + u];
            g_Wc[idx] = tot;
        }
        if (t < N_CLASSES) {
            float s2 = bfc[t];
            for (int o = 0; o < OUT_FEATS; o++)
                s2 += b2[o] * Wfc[o * N_CLASSES + t];
            g_bc[t] = s2;
        }
    }
}

// ---------------- GEMM1: tf32 MMA, per-warp cp.async pipeline (barrier-free) -------
__device__ __forceinline__ void mma_tf32(float& c0, float& c1, float& c2, float& c3,
                                         uint32_t a0, uint32_t a1, uint32_t a2, uint32_t a3,
                                         uint32_t b0, uint32_t b1) {
    asm volatile("mma.sync.aligned.m16n8k8.row.col.f32.tf32.tf32.f32 "
                 "{%0,%1,%2,%3}, {%4,%5,%6,%7}, {%8,%9}, {%0,%1,%2,%3};"
                 : "+f"(c0), "+f"(c1), "+f"(c2), "+f"(c3)
                 : "r"(a0), "r"(a1), "r"(a2), "r"(a3), "r"(b0), "r"(b1));
}
__device__ __forceinline__ void cp16(uint32_t smem_addr, const void* gptr) {
    asm volatile("cp.async.ca.shared.global [%0], [%1], 16;"
                 :: "r"(smem_addr), "l"(gptr));
}

__global__ __launch_bounds__(256, 3)
void gemm1_kernel(const float* __restrict__ feat) {
    __shared__ __align__(16) uint32_t SW[IN_FEATS * HIDDEN];      // 32KB tf32 W1
    __shared__ __align__(16) uint32_t SA[8 * 2 * SA_STG];         // per-warp double buffer

    int tid  = threadIdx.x;
    int lane = tid & 31;
    int warp = tid >> 5;
    int g = lane >> 2;
    int t = lane & 3;
    int baseRow = blockIdx.x * G1_ROWS;
    int wRow = baseRow + warp * 16;

    uint32_t swB = (uint32_t)__cvta_generic_to_shared(SW);
    uint32_t saB = (uint32_t)__cvta_generic_to_shared(SA) + (warp * 2 * SA_STG) * 4;

    // stage W1 via cp.async (group 0): 2048 chunks / 256 threads = 8 each
    #pragma unroll
    for (int i = 0; i < 8; i++) {
        int c = tid + i * 256;
        cp16(swB + c * 16, g_w1t + c * 4);
    }
    asm volatile("cp.async.commit_group;");

    // per-warp A-tile issue: tile kt -> stage st. 128 chunks/warp, 4 per lane.
    auto issueA = [&](int kt, int st) {
        #pragma unroll
        for (int i = 0; i < 4; i++) {
            int c = lane + i * 32;
            int row = c >> 3, cw = c & 7;
            int gr = wRow + row; if (gr >= N_NODES) gr = N_NODES - 1;
            cp16(saB + (st * SA_STG + row * SA_LD + cw * 4) * 4,
                 feat + (size_t)gr * IN_FEATS + kt * G1_KT + cw * 4);
        }
        asm volatile("cp.async.commit_group;");
    };

    issueA(0, 0);   // group 1
    issueA(1, 1);   // group 2

    // one block barrier: W1 visible to all warps (own W-copies done at wait below)
    asm volatile("cp.async.wait_group 2;");   // W (group 0) complete; A0, A1 pending
    __syncthreads();

    float c[8];
    #pragma unroll
    for (int i = 0; i < 8; i++) c[i] = 0.f;

    int arow0 = g * SA_LD;
    int arow1 = (g + 8) * SA_LD;

    #pragma unroll 1
    for (int kt = 0; kt < G1_NKT; kt++) {
        int st = kt & 1;
        // tile kt = group kt+1; latest committed = group kt+2 (except last iter)
        if (kt == G1_NKT - 1)
            asm volatile("cp.async.wait_group 0;");
        else
            asm volatile("cp.async.wait_group 1;");
        __syncwarp();

        int sa0 = st * SA_STG;
        #pragma unroll
        for (int ks = 0; ks < 4; ks++) {
            int k0 = ks * 8;
            uint32_t a0 = bits2tf32(SA[(saB - (uint32_t)__cvta_generic_to_shared(SA)) / 4 + sa0 + arow0 + k0 + t]);
            uint32_t a1 = bits2tf32(SA[(saB - (uint32_t)__cvta_generic_to_shared(SA)) / 4 + sa0 + arow1 + k0 + t]);
            uint32_t a2 = bits2tf32(SA[(saB - (uint32_t)__cvta_generic_to_shared(SA)) / 4 + sa0 + arow0 + k0 + t + 4]);
            uint32_t a3 = bits2tf32(SA[(saB - (uint32_t)__cvta_generic_to_shared(SA)) / 4 + sa0 + arow1 + k0 + t + 4]);
            int kg = kt * G1_KT + k0;
            uint32_t b0 = SW[(kg + t) * 16 + g];
            uint32_t b1 = SW[(kg + t + 4) * 16 + g];
            mma_tf32(c[0], c[1], c[2], c[3], a0, a1, a2, a3, b0, b1);
            uint32_t b2 = SW[(kg + t) * 16 + 8 + g];
            uint32_t b3 = SW[(kg + t + 4) * 16 + 8 + g];
            mma_tf32(c[4], c[5], c[6], c[7], a0, a1, a2, a3, b2, b3);
        }
        __syncwarp();                 // all lanes done reading stage st
        if (kt + 2 < G1_NKT) issueA(kt + 2, st);
    }

    if (wRow < N_NODES) {             // N_NODES % 16 == 0 -> full warp-tile valid
        int rowA = wRow + g;
        int rowB = rowA + 8;
        float sA = g_ns[rowA];
        float sB = g_ns[rowB];
        float2 v;
        v.x = sA * c[0]; v.y = sA * c[1];
        *(float2*)(g_p1 + (size_t)rowA * 16 + 2 * t) = v;
        v.x = sB * c[2]; v.y = sB * c[3];
        *(float2*)(g_p1 + (size_t)rowB * 16 + 2 * t) = v;
        v.x = sA * c[4]; v.y = sA * c[5];
        *(float2*)(g_p1 + (size_t)rowA * 16 + 8 + 2 * t) = v;
        v.x = sB * c[6]; v.y = sB * c[7];
        *(float2*)(g_p1 + (size_t)rowB * 16 + 8 + 2 * t) = v;
    }
}

// ---------------- scan stage 1 ----------------
__global__ __launch_bounds__(SCAN_BLK)
void scan1_kernel() {
    __shared__ int sh[SCAN_BLK];
    int i = blockIdx.x * SCAN_BLK + threadIdx.x;
    int v = (i < N_NODES) ? g_degd[i] : 0;
    sh[threadIdx.x] = v;
    __syncthreads();
    #pragma unroll
    for (int off = 1; off < SCAN_BLK; off <<= 1) {
        int t = (threadIdx.x >= off) ? sh[threadIdx.x - off] : 0;
        __syncthreads();
        sh[threadIdx.x] += t;
        __syncthreads();
    }
    if (i <= N_NODES) g_rowptr[i] = sh[threadIdx.x] - v;
    if (threadIdx.x == SCAN_BLK - 1) g_blksum[blockIdx.x] = sh[SCAN_BLK - 1];
}

// ---------------- scan stage 2 ----------------
__global__ __launch_bounds__(256)
void scan2_kernel() {
    __shared__ int sh[256];
    int t = threadIdx.x;
    int v = (t < N_SCAN_BLKS) ? g_blksum[t] : 0;
    sh[t] = v;
    __syncthreads();
    #pragma unroll
    for (int off = 1; off < 256; off <<= 1) {
        int x = (t >= off) ? sh[t - off] : 0;
        __syncthreads();
        sh[t] += x;
        __syncthreads();
    }
    g_blksum[t] = sh[t] - v;
}

// ---------------- scan stage 3 ----------------
__global__ __launch_bounds__(SCAN_BLK)
void scan3_kernel() {
    int i = blockIdx.x * SCAN_BLK + threadIdx.x;
    if (i <= N_NODES) g_rowptr[i] += g_blksum[blockIdx.x];
    if (i < N_NODES)  g_degd[i] = 0;
}

// ---------------- CSR permute ----------------
__global__ void permute_kernel(const int* __restrict__ src, const int* __restrict__ dst) {
    int e = blockIdx.x * blockDim.x + threadIdx.x;
    if (e >= N_EDGES) return;
    int d = dst[e];
    int pos = g_rowptr[d] + atomicAdd(&g_degd[d], 1);
    g_csrc[pos] = src[e];
}

// ---------------- gather layer 1 ----------------
__global__ __launch_bounds__(256)
void gather1_kernel(const float* __restrict__ b1) {
    int g = blockIdx.x * blockDim.x + threadIdx.x;
    int n = g >> 2, c = g & 3;
    if (n >= N_NODES) return;
    int beg = g_rowptr[n], end = g_rowptr[n + 1];
    float4 acc = make_float4(0.f, 0.f, 0.f, 0.f);
    int t = beg;
    for (; t + 1 < end; t += 2) {
        int s0 = g_csrc[t], s1 = g_csrc[t + 1];
        float4 v0 = *(const float4*)(g_p1 + (size_t)s0 * 16 + c * 4);
        float4 v1 = *(const float4*)(g_p1 + (size_t)s1 * 16 + c * 4);
        acc.x += v0.x + v1.x; acc.y += v0.y + v1.y;
        acc.z += v0.z + v1.z; acc.w += v0.w + v1.w;
    }
    if (t < end) {
        int s0 = g_csrc[t];
        float4 v0 = *(const float4*)(g_p1 + (size_t)s0 * 16 + c * 4);
        acc.x += v0.x; acc.y += v0.y; acc.z += v0.z; acc.w += v0.w;
    }
    float ns = g_ns[n], nd = g_nd[n];
    float4 o;
    o.x = ns * fmaxf(fmaf(nd, acc.x, b1[c * 4 + 0]), 0.f);
    o.y = ns * fmaxf(fmaf(nd, acc.y, b1[c * 4 + 1]), 0.f);
    o.z = ns * fmaxf(fmaf(nd, acc.z, b1[c * 4 + 2]), 0.f);
    o.w = ns * fmaxf(fmaf(nd, acc.w, b1[c * 4 + 3]), 0.f);
    ((float4*)g_q)[n * 4 + c] = o;
}

// ---------------- gather layer 2 + final projection ----------------
__global__ __launch_bounds__(256)
void gather2_kernel(float* __restrict__ out) {
    int g = blockIdx.x * blockDim.x + threadIdx.x;
    int n = g >> 2, c = g & 3;
    if (n >= N_NODES) return;
    int beg = g_rowptr[n], end = g_rowptr[n + 1];
    float4 acc = make_float4(0.f, 0.f, 0.f, 0.f);
    int t = beg;
    for (; t + 1 < end; t += 2) {
        int s0 = g_csrc[t], s1 = g_csrc[t + 1];
        float4 v0 = *(const float4*)(g_q + (size_t)s0 * 16 + c * 4);
        float4 v1 = *(const float4*)(g_q + (size_t)s1 * 16 + c * 4);
        acc.x += v0.x + v1.x; acc.y += v0.y + v1.y;
        acc.z += v0.z + v1.z; acc.w += v0.w + v1.w;
    }
    if (t < end) {
        int s0 = g_csrc[t];
        float4 v0 = *(const float4*)(g_q + (size_t)s0 * 16 + c * 4);
        acc.x += v0.x; acc.y += v0.y; acc.z += v0.z; acc.w += v0.w;
    }
    int o0 = c * 4;
    float c0 = acc.x * g_Wc[(o0 + 0) * 3 + 0] + acc.y * g_Wc[(o0 + 1) * 3 + 0]
             + acc.z * g_Wc[(o0 + 2) * 3 + 0] + acc.w * g_Wc[(o0 + 3) * 3 + 0];
    float c1 = acc.x * g_Wc[(o0 + 0) * 3 + 1] + acc.y * g_Wc[(o0 + 1) * 3 + 1]
             + acc.z * g_Wc[(o0 + 2) * 3 + 1] + acc.w * g_Wc[(o0 + 3) * 3 + 1];
    float c2 = acc.x * g_Wc[(o0 + 0) * 3 + 2] + acc.y * g_Wc[(o0 + 1) * 3 + 2]
             + acc.z * g_Wc[(o0 + 2) * 3 + 2] + acc.w * g_Wc[(o0 + 3) * 3 + 2];
    c0 += __shfl_xor_sync(0xffffffffu, c0, 1);
    c0 += __shfl_xor_sync(0xffffffffu, c0, 2);
    c1 += __shfl_xor_sync(0xffffffffu, c1, 1);
    c1 += __shfl_xor_sync(0xffffffffu, c1, 2);
    c2 += __shfl_xor_sync(0xffffffffu, c2, 1);
    c2 += __shfl_xor_sync(0xffffffffu, c2, 2);
    if (c == 0) {
        float dn = g_nd[n];
        out[n * 3 + 0] = fmaf(dn, c0, g_bc[0]);
        out[n * 3 + 1] = fmaf(dn, c1, g_bc[1]);
        out[n * 3 + 2] = fmaf(dn, c2, g_bc[2]);
    }
}

// ---------------- launch: fork-join (gemm1 || scans+permute) ----------------
extern "C" void kernel_launch(void* const* d_in, const int* in_sizes, int n_in,
                              void* d_out, int out_size) {
    const float* feat = (const float*)d_in[0];
    const int*   src  = (const int*)d_in[1];
    const int*   dst  = (const int*)d_in[2];
    const float* W1   = (const float*)d_in[3];
    const float* b1   = (const float*)d_in[4];
    const float* W2   = (const float*)d_in[5];
    const float* b2   = (const float*)d_in[6];
    const float* Wfc  = (const float*)d_in[7];
    const float* bfc  = (const float*)d_in[8];
    float*       out  = (float*)d_out;

    static cudaStream_t s2 = nullptr;
    static cudaEvent_t  evFork = nullptr, evJoin = nullptr;
    if (!s2) {
        cudaStreamCreateWithFlags(&s2, cudaStreamNonBlocking);
        cudaEventCreateWithFlags(&evFork, cudaEventDisableTiming);
        cudaEventCreateWithFlags(&evJoin, cudaEventDisableTiming);
    }

    const int TB = 256;
    int zb  = (IN_FEATS * HIDDEN + TB - 1) / TB;
    if (zb < (N_NODES / 4 + TB - 1) / TB) zb = (N_NODES / 4 + TB - 1) / TB;
    int db  = (N_EDGES / 4 + TB - 1) / TB;
    int nwb = (N_NODES + 383) / 384;
    int eb  = (N_EDGES + TB - 1) / TB;
    int gb  = (N_NODES * 4 + TB - 1) / TB;
    int g1b = (N_NODES + G1_ROWS - 1) / G1_ROWS;   // 782

    zero_kernel   <<<zb, TB>>>(W1);
    deg_kernel    <<<db, TB>>>(src, dst);
    norm_wc_kernel<<<nwb, 384>>>(W2, b2, Wfc, bfc);

    // fork: branch B (scans+permute) runs on s2, concurrent with gemm1
    cudaEventRecord(evFork, 0);
    cudaStreamWaitEvent(s2, evFork, 0);

    gemm1_kernel  <<<g1b, 256>>>(feat);            // index 3 -> profiled

    scan1_kernel  <<<N_SCAN_BLKS, SCAN_BLK, 0, s2>>>();
    scan2_kernel  <<<1, 256, 0, s2>>>();
    scan3_kernel  <<<N_SCAN_BLKS, SCAN_BLK, 0, s2>>>();
    permute_kernel<<<eb, TB, 0, s2>>>(src, dst);

    // join
    cudaEventRecord(evJoin, s2);
    cudaStreamWaitEvent(0, evJoin, 0);

    gather1_kernel<<<gb, TB>>>(b1);
    gather2_kernel<<<gb, TB>>>(out);
}

// round 16
// speedup vs baseline: 4.9973x; 1.0817x over previous
#include <cuda_runtime.h>
#include <cstdint>

#define N_NODES 100000
#define N_EDGES 3200000
#define IN_FEATS 512
#define HIDDEN 16
#define OUT_FEATS 128
#define N_CLASSES 3

#define SCAN_BLK 512
#define N_SCAN_BLKS ((N_NODES + SCAN_BLK) / SCAN_BLK + 1)

// gemm1: 128 rows/CTA; per-warp 16-row tile; K-tiles of 32, per-warp double buffer
#define G1_ROWS 128
#define G1_KT   32
#define G1_NKT  (IN_FEATS / G1_KT)   // 16
#define SA_LD   36                   // 32 + 4 pad words (conflict-free)
#define SA_STG  (16 * SA_LD)         // 576 words per warp-stage

// ---------------- scratch (device globals; touched ONLY from device code) ----------
__device__ __align__(16) float    g_p1 [N_NODES * HIDDEN];
__device__ __align__(16) float    g_q  [N_NODES * HIDDEN];
__device__ __align__(16) float    g_ns [N_NODES];
__device__ __align__(16) float    g_nd [N_NODES];
__device__ __align__(16) int      g_degs[N_NODES];
__device__ __align__(16) int      g_degd[N_NODES];
__device__ __align__(16) int      g_rowptr[N_NODES + 1];
__device__ __align__(16) int      g_blksum[256];
__device__ __align__(16) int      g_csrc[N_EDGES];
__device__ __align__(16) uint32_t g_w1t[IN_FEATS * HIDDEN];   // W1 as tf32 bits
__device__ __align__(16) float    g_Wc [HIDDEN * N_CLASSES];
__device__ __align__(16) float    g_bc [N_CLASSES];

__device__ __forceinline__ uint32_t f2tf32(float x) {
    uint32_t r;
    asm("cvt.rna.tf32.f32 %0, %1;" : "=r"(r) : "f"(x));
    return r;
}
__device__ __forceinline__ uint32_t bits2tf32(uint32_t xb) {
    uint32_t r;
    asm("cvt.rna.tf32.f32 %0, %1;" : "=r"(r) : "f"(__uint_as_float(xb)));
    return r;
}

// ---------------- zero degrees + build tf32 W1 ----------------
__global__ void zero_kernel(const float* __restrict__ W1) {
    int i = blockIdx.x * blockDim.x + threadIdx.x;
    if (i < N_NODES / 4) {
        ((int4*)g_degs)[i] = make_int4(0, 0, 0, 0);
        ((int4*)g_degd)[i] = make_int4(0, 0, 0, 0);
    }
    if (i < IN_FEATS * HIDDEN)
        g_w1t[i] = f2tf32(W1[i]);
}

// ---------------- degree histogram, 4 edges per thread ----------------
__global__ void deg_kernel(const int* __restrict__ src, const int* __restrict__ dst) {
    int t = blockIdx.x * blockDim.x + threadIdx.x;
    if (t >= N_EDGES / 4) return;
    int4 s4 = ((const int4*)src)[t];
    int4 d4 = ((const int4*)dst)[t];
    atomicAdd(&g_degs[s4.x], 1); atomicAdd(&g_degs[s4.y], 1);
    atomicAdd(&g_degs[s4.z], 1); atomicAdd(&g_degs[s4.w], 1);
    atomicAdd(&g_degd[d4.x], 1); atomicAdd(&g_degd[d4.y], 1);
    atomicAdd(&g_degd[d4.z], 1); atomicAdd(&g_degd[d4.w], 1);
}

// ---------------- norms everywhere; block 0 additionally computes Wc, bc ----------
__global__ __launch_bounds__(384)
void norm_wc_kernel(const float* __restrict__ W2, const float* __restrict__ b2,
                    const float* __restrict__ Wfc, const float* __restrict__ bfc) {
    int n = blockIdx.x * 384 + threadIdx.x;
    if (n < N_NODES) {
        g_ns[n] = rsqrtf(fmaxf((float)g_degs[n], 1.0f));
        g_nd[n] = rsqrtf(fmaxf((float)g_degd[n], 1.0f));
    }
    if (blockIdx.x == 0) {
        __shared__ float part[384];
        int t = threadIdx.x;
        int o0 = (t & 7) * 16;
        int idx = t >> 3;
        int k = idx / N_CLASSES, c = idx % N_CLASSES;
        float s = 0.f;
        #pragma unroll
        for (int o = 0; o < 16; o++)
            s += W2[k * OUT_FEATS + o0 + o] * Wfc[(o0 + o) * N_CLASSES + c];
        part[t] = s;
        __syncthreads();
        if ((t & 7) == 0) {
            float tot = 0.f;
            #pragma unroll
            for (int u = 0; u < 8; u++) tot += part[t + u];
            g_Wc[idx] = tot;
        }
        if (t < N_CLASSES) {
            float s2 = bfc[t];
            for (int o = 0; o < OUT_FEATS; o++)
                s2 += b2[o] * Wfc[o * N_CLASSES + t];
            g_bc[t] = s2;
        }
    }
}

// ---------------- GEMM1: tf32 MMA, per-warp cp.async A; B via L1 (__ldg) ----------
__device__ __forceinline__ void mma_tf32(float& c0, float& c1, float& c2, float& c3,
                                         uint32_t a0, uint32_t a1, uint32_t a2, uint32_t a3,
                                         uint32_t b0, uint32_t b1) {
    asm volatile("mma.sync.aligned.m16n8k8.row.col.f32.tf32.tf32.f32 "
                 "{%0,%1,%2,%3}, {%4,%5,%6,%7}, {%8,%9}, {%0,%1,%2,%3};"
                 : "+f"(c0), "+f"(c1), "+f"(c2), "+f"(c3)
                 : "r"(a0), "r"(a1), "r"(a2), "r"(a3), "r"(b0), "r"(b1));
}
__device__ __forceinline__ void cp16(uint32_t smem_addr, const void* gptr) {
    asm volatile("cp.async.ca.shared.global [%0], [%1], 16;"
                 :: "r"(smem_addr), "l"(gptr));
}

__global__ __launch_bounds__(256, 5)
void gemm1_kernel(const float* __restrict__ feat) {
    __shared__ __align__(16) uint32_t SA[8 * 2 * SA_STG];   // 36KB: per-warp dbl buffer

    int tid  = threadIdx.x;
    int lane = tid & 31;
    int warp = tid >> 5;
    int g = lane >> 2;
    int t = lane & 3;
    int baseRow = blockIdx.x * G1_ROWS;
    int wRow = baseRow + warp * 16;

    uint32_t* sa = SA + warp * 2 * SA_STG;
    uint32_t saB = (uint32_t)__cvta_generic_to_shared(sa);

    // per-warp A-tile issue: tile kt -> stage st. 128 chunks/warp, 4 per lane.
    auto issueA = [&](int kt, int st) {
        #pragma unroll
        for (int i = 0; i < 4; i++) {
            int c = lane + i * 32;
            int row = c >> 3, cw = c & 7;
            int gr = wRow + row; if (gr >= N_NODES) gr = N_NODES - 1;
            cp16(saB + (st * SA_STG + row * SA_LD + cw * 4) * 4,
                 feat + (size_t)gr * IN_FEATS + kt * G1_KT + cw * 4);
        }
        asm volatile("cp.async.commit_group;");
    };

    issueA(0, 0);   // group 0
    issueA(1, 1);   // group 1

    float c[8];
    #pragma unroll
    for (int i = 0; i < 8; i++) c[i] = 0.f;

    int arow0 = g * SA_LD;
    int arow1 = (g + 8) * SA_LD;

    #pragma unroll 1
    for (int kt = 0; kt < G1_NKT; kt++) {
        int st = kt & 1;
        // tile kt = group kt; latest committed = group kt+1 except final iteration
        if (kt == G1_NKT - 1)
            asm volatile("cp.async.wait_group 0;");
        else
            asm volatile("cp.async.wait_group 1;");
        __syncwarp();

        int sa0 = st * SA_STG;
        #pragma unroll
        for (int ks = 0; ks < 4; ks++) {
            int k0 = ks * 8;
            uint32_t a0 = bits2tf32(sa[sa0 + arow0 + k0 + t]);
            uint32_t a1 = bits2tf32(sa[sa0 + arow1 + k0 + t]);
            uint32_t a2 = bits2tf32(sa[sa0 + arow0 + k0 + t + 4]);
            uint32_t a3 = bits2tf32(sa[sa0 + arow1 + k0 + t + 4]);
            int kg = kt * G1_KT + k0;
            uint32_t b0 = __ldg(&g_w1t[(kg + t) * 16 + g]);
            uint32_t b1 = __ldg(&g_w1t[(kg + t + 4) * 16 + g]);
            mma_tf32(c[0], c[1], c[2], c[3], a0, a1, a2, a3, b0, b1);
            uint32_t b2 = __ldg(&g_w1t[(kg + t) * 16 + 8 + g]);
            uint32_t b3 = __ldg(&g_w1t[(kg + t + 4) * 16 + 8 + g]);
            mma_tf32(c[4], c[5], c[6], c[7], a0, a1, a2, a3, b2, b3);
        }
        __syncwarp();                 // all lanes done reading stage st
        if (kt + 2 < G1_NKT) issueA(kt + 2, st);
    }

    if (wRow < N_NODES) {             // N_NODES % 16 == 0 -> full warp-tile valid
        int rowA = wRow + g;
        int rowB = rowA + 8;
        float sA = g_ns[rowA];
        float sB = g_ns[rowB];
        float2 v;
        v.x = sA * c[0]; v.y = sA * c[1];
        *(float2*)(g_p1 + (size_t)rowA * 16 + 2 * t) = v;
        v.x = sB * c[2]; v.y = sB * c[3];
        *(float2*)(g_p1 + (size_t)rowB * 16 + 2 * t) = v;
        v.x = sA * c[4]; v.y = sA * c[5];
        *(float2*)(g_p1 + (size_t)rowA * 16 + 8 + 2 * t) = v;
        v.x = sB * c[6]; v.y = sB * c[7];
        *(float2*)(g_p1 + (size_t)rowB * 16 + 8 + 2 * t) = v;
    }
}

// ---------------- scan stage 1 ----------------
__global__ __launch_bounds__(SCAN_BLK)
void scan1_kernel() {
    __shared__ int sh[SCAN_BLK];
    int i = blockIdx.x * SCAN_BLK + threadIdx.x;
    int v = (i < N_NODES) ? g_degd[i] : 0;
    sh[threadIdx.x] = v;
    __syncthreads();
    #pragma unroll
    for (int off = 1; off < SCAN_BLK; off <<= 1) {
        int t = (threadIdx.x >= off) ? sh[threadIdx.x - off] : 0;
        __syncthreads();
        sh[threadIdx.x] += t;
        __syncthreads();
    }
    if (i <= N_NODES) g_rowptr[i] = sh[threadIdx.x] - v;
    if (threadIdx.x == SCAN_BLK - 1) g_blksum[blockIdx.x] = sh[SCAN_BLK - 1];
}

// ---------------- scan stage 2 ----------------
__global__ __launch_bounds__(256)
void scan2_kernel() {
    __shared__ int sh[256];
    int t = threadIdx.x;
    int v = (t < N_SCAN_BLKS) ? g_blksum[t] : 0;
    sh[t] = v;
    __syncthreads();
    #pragma unroll
    for (int off = 1; off < 256; off <<= 1) {
        int x = (t >= off) ? sh[t - off] : 0;
        __syncthreads();
        sh[t] += x;
        __syncthreads();
    }
    g_blksum[t] = sh[t] - v;
}

// ---------------- scan stage 3 ----------------
__global__ __launch_bounds__(SCAN_BLK)
void scan3_kernel() {
    int i = blockIdx.x * SCAN_BLK + threadIdx.x;
    if (i <= N_NODES) g_rowptr[i] += g_blksum[blockIdx.x];
    if (i < N_NODES)  g_degd[i] = 0;
}

// ---------------- CSR permute ----------------
__global__ void permute_kernel(const int* __restrict__ src, const int* __restrict__ dst) {
    int e = blockIdx.x * blockDim.x + threadIdx.x;
    if (e >= N_EDGES) return;
    int d = dst[e];
    int pos = g_rowptr[d] + atomicAdd(&g_degd[d], 1);
    g_csrc[pos] = src[e];
}

// ---------------- gather layer 1 (4-edge unroll) ----------------
__global__ __launch_bounds__(256)
void gather1_kernel(const float* __restrict__ b1) {
    int g = blockIdx.x * blockDim.x + threadIdx.x;
    int n = g >> 2, c = g & 3;
    if (n >= N_NODES) return;
    int beg = g_rowptr[n], end = g_rowptr[n + 1];
    float4 acc = make_float4(0.f, 0.f, 0.f, 0.f);
    int t = beg;
    for (; t + 3 < end; t += 4) {
        int s0 = g_csrc[t], s1 = g_csrc[t + 1], s2 = g_csrc[t + 2], s3 = g_csrc[t + 3];
        float4 v0 = *(const float4*)(g_p1 + (size_t)s0 * 16 + c * 4);
        float4 v1 = *(const float4*)(g_p1 + (size_t)s1 * 16 + c * 4);
        float4 v2 = *(const float4*)(g_p1 + (size_t)s2 * 16 + c * 4);
        float4 v3 = *(const float4*)(g_p1 + (size_t)s3 * 16 + c * 4);
        acc.x += (v0.x + v1.x) + (v2.x + v3.x);
        acc.y += (v0.y + v1.y) + (v2.y + v3.y);
        acc.z += (v0.z + v1.z) + (v2.z + v3.z);
        acc.w += (v0.w + v1.w) + (v2.w + v3.w);
    }
    for (; t < end; t++) {
        int s0 = g_csrc[t];
        float4 v0 = *(const float4*)(g_p1 + (size_t)s0 * 16 + c * 4);
        acc.x += v0.x; acc.y += v0.y; acc.z += v0.z; acc.w += v0.w;
    }
    float ns = g_ns[n], nd = g_nd[n];
    float4 o;
    o.x = ns * fmaxf(fmaf(nd, acc.x, b1[c * 4 + 0]), 0.f);
    o.y = ns * fmaxf(fmaf(nd, acc.y, b1[c * 4 + 1]), 0.f);
    o.z = ns * fmaxf(fmaf(nd, acc.z, b1[c * 4 + 2]), 0.f);
    o.w = ns * fmaxf(fmaf(nd, acc.w, b1[c * 4 + 3]), 0.f);
    ((float4*)g_q)[n * 4 + c] = o;
}

// ---------------- gather layer 2 + final projection (4-edge unroll) ---------------
__global__ __launch_bounds__(256)
void gather2_kernel(float* __restrict__ out) {
    int g = blockIdx.x * blockDim.x + threadIdx.x;
    int n = g >> 2, c = g & 3;
    if (n >= N_NODES) return;
    int beg = g_rowptr[n], end = g_rowptr[n + 1];
    float4 acc = make_float4(0.f, 0.f, 0.f, 0.f);
    int t = beg;
    for (; t + 3 < end; t += 4) {
        int s0 = g_csrc[t], s1 = g_csrc[t + 1], s2 = g_csrc[t + 2], s3 = g_csrc[t + 3];
        float4 v0 = *(const float4*)(g_q + (size_t)s0 * 16 + c * 4);
        float4 v1 = *(const float4*)(g_q + (size_t)s1 * 16 + c * 4);
        float4 v2 = *(const float4*)(g_q + (size_t)s2 * 16 + c * 4);
        float4 v3 = *(const float4*)(g_q + (size_t)s3 * 16 + c * 4);
        acc.x += (v0.x + v1.x) + (v2.x + v3.x);
        acc.y += (v0.y + v1.y) + (v2.y + v3.y);
        acc.z += (v0.z + v1.z) + (v2.z + v3.z);
        acc.w += (v0.w + v1.w) + (v2.w + v3.w);
    }
    for (; t < end; t++) {
        int s0 = g_csrc[t];
        float4 v0 = *(const float4*)(g_q + (size_t)s0 * 16 + c * 4);
        acc.x += v0.x; acc.y += v0.y; acc.z += v0.z; acc.w += v0.w;
    }
    int o0 = c * 4;
    float c0 = acc.x * g_Wc[(o0 + 0) * 3 + 0] + acc.y * g_Wc[(o0 + 1) * 3 + 0]
             + acc.z * g_Wc[(o0 + 2) * 3 + 0] + acc.w * g_Wc[(o0 + 3) * 3 + 0];
    float c1 = acc.x * g_Wc[(o0 + 0) * 3 + 1] + acc.y * g_Wc[(o0 + 1) * 3 + 1]
             + acc.z * g_Wc[(o0 + 2) * 3 + 1] + acc.w * g_Wc[(o0 + 3) * 3 + 1];
    float c2 = acc.x * g_Wc[(o0 + 0) * 3 + 2] + acc.y * g_Wc[(o0 + 1) * 3 + 2]
             + acc.z * g_Wc[(o0 + 2) * 3 + 2] + acc.w * g_Wc[(o0 + 3) * 3 + 2];
    c0 += __shfl_xor_sync(0xffffffffu, c0, 1);
    c0 += __shfl_xor_sync(0xffffffffu, c0, 2);
    c1 += __shfl_xor_sync(0xffffffffu, c1, 1);
    c1 += __shfl_xor_sync(0xffffffffu, c1, 2);
    c2 += __shfl_xor_sync(0xffffffffu, c2, 1);
    c2 += __shfl_xor_sync(0xffffffffu, c2, 2);
    if (c == 0) {
        float dn = g_nd[n];
        out[n * 3 + 0] = fmaf(dn, c0, g_bc[0]);
        out[n * 3 + 1] = fmaf(dn, c1, g_bc[1]);
        out[n * 3 + 2] = fmaf(dn, c2, g_bc[2]);
    }
}

// ---------------- launch: fork-join (gemm1 || scans+permute) ----------------
extern "C" void kernel_launch(void* const* d_in, const int* in_sizes, int n_in,
                              void* d_out, int out_size) {
    const float* feat = (const float*)d_in[0];
    const int*   src  = (const int*)d_in[1];
    const int*   dst  = (const int*)d_in[2];
    const float* W1   = (const float*)d_in[3];
    const float* b1   = (const float*)d_in[4];
    const float* W2   = (const float*)d_in[5];
    const float* b2   = (const float*)d_in[6];
    const float* Wfc  = (const float*)d_in[7];
    const float* bfc  = (const float*)d_in[8];
    float*       out  = (float*)d_out;

    static cudaStream_t s2 = nullptr;
    static cudaEvent_t  evFork = nullptr, evJoin = nullptr;
    if (!s2) {
        cudaStreamCreateWithFlags(&s2, cudaStreamNonBlocking);
        cudaEventCreateWithFlags(&evFork, cudaEventDisableTiming);
        cudaEventCreateWithFlags(&evJoin, cudaEventDisableTiming);
    }

    const int TB = 256;
    int zb  = (IN_FEATS * HIDDEN + TB - 1) / TB;
    if (zb < (N_NODES / 4 + TB - 1) / TB) zb = (N_NODES / 4 + TB - 1) / TB;
    int db  = (N_EDGES / 4 + TB - 1) / TB;
    int nwb = (N_NODES + 383) / 384;
    int eb  = (N_EDGES + TB - 1) / TB;
    int gb  = (N_NODES * 4 + TB - 1) / TB;
    int g1b = (N_NODES + G1_ROWS - 1) / G1_ROWS;   // 782

    zero_kernel   <<<zb, TB>>>(W1);
    deg_kernel    <<<db, TB>>>(src, dst);
    norm_wc_kernel<<<nwb, 384>>>(W2, b2, Wfc, bfc);

    // fork: branch B (scans+permute) runs on s2, concurrent with gemm1
    cudaEventRecord(evFork, 0);
    cudaStreamWaitEvent(s2, evFork, 0);

    gemm1_kernel  <<<g1b, 256>>>(feat);            // index 3 -> profiled

    scan1_kernel  <<<N_SCAN_BLKS, SCAN_BLK, 0, s2>>>();
    scan2_kernel  <<<1, 256, 0, s2>>>();
    scan3_kernel  <<<N_SCAN_BLKS, SCAN_BLK, 0, s2>>>();
    permute_kernel<<<eb, TB, 0, s2>>>(src, dst);

    // join
    cudaEventRecord(evJoin, s2);
    cudaStreamWaitEvent(0, evJoin, 0);

    gather1_kernel<<<gb, TB>>>(b1);
    gather2_kernel<<<gb, TB>>>(out);
}